// round 11
// baseline (speedup 1.0000x reference)
#include <cuda_runtime.h>
#include <cuda_bf16.h>
#include <cstdint>
#include <math.h>

#define F   128
#define R   32
#define TP  64       // pairs per tile in k_pairs
#define NT  256

// ---------------------------------------------------------------- scratch
__device__ float g_h  [100000 * 128];
__device__ float g_acc[100000 * 128];
__device__ unsigned char g_W2T [2][32768];  // Wf2^T  [n][k] bf16 hi/lo, 256B rows, XOR-swizzled
__device__ unsigned char g_WinT[2][32768];  // W_in^T
__device__ unsigned char g_Wo1T[2][32768];  // Wo1^T
__device__ unsigned char g_Wo2T[2][32768];  // Wo2^T

// ---------------------------------------------------------------- helpers
__device__ __forceinline__ uint32_t smem_u32(const void* p) {
    uint32_t a;
    asm("{ .reg .u64 t; cvta.to.shared.u64 t, %1; cvt.u32.u64 %0, t; }" : "=r"(a) : "l"(p));
    return a;
}
__device__ __forceinline__ void barn(int id) {          // named barrier, 128 threads
    asm volatile("bar.sync %0, %1;" :: "r"(id), "r"(128) : "memory");
}
__device__ __forceinline__ float sspf(float x) {
    float e = __expf(-fabsf(x));
    return fmaxf(x, 0.0f) + __logf(1.0f + e) - 0.6931471805599453f;
}
__device__ __forceinline__ void red_add_v4(float* p, float4 v) {
    asm volatile("red.global.add.v4.f32 [%0], {%1,%2,%3,%4};"
                 :: "l"(p), "f"(v.x), "f"(v.y), "f"(v.z), "f"(v.w) : "memory");
}
__device__ __forceinline__ void split_pack(float a, float b, uint32_t& hi, uint32_t& lo) {
    __nv_bfloat16 ah = __float2bfloat16(a), bh = __float2bfloat16(b);
    float ar = a - __bfloat162float(ah);
    float br = b - __bfloat162float(bh);
    __nv_bfloat16 al = __float2bfloat16(ar), bl = __float2bfloat16(br);
    hi = ((uint32_t)__bfloat16_as_ushort(bh) << 16) | (uint32_t)__bfloat16_as_ushort(ah);
    lo = ((uint32_t)__bfloat16_as_ushort(bl) << 16) | (uint32_t)__bfloat16_as_ushort(al);
}
__device__ __forceinline__ void mma16816(float* c, const uint32_t* a, const uint32_t* b) {
    asm volatile("mma.sync.aligned.m16n8k16.row.col.f32.bf16.bf16.f32 "
                 "{%0,%1,%2,%3}, {%4,%5,%6,%7}, {%8,%9}, {%0,%1,%2,%3};"
                 : "+f"(c[0]), "+f"(c[1]), "+f"(c[2]), "+f"(c[3])
                 : "r"(a[0]), "r"(a[1]), "r"(a[2]), "r"(a[3]), "r"(b[0]), "r"(b[1]));
}
__device__ __forceinline__ void ldsm_x4(uint32_t* r, uint32_t addr) {
    asm volatile("ldmatrix.sync.aligned.m8n8.x4.shared.b16 {%0,%1,%2,%3}, [%4];"
                 : "=r"(r[0]), "=r"(r[1]), "=r"(r[2]), "=r"(r[3]) : "r"(addr));
}
// interleaved 3-term split MMA: chains c0/c1 alternate (dep distance 2)
#define MMA6(c0, c1, ah, al, bh, bl) do {          \
    mma16816(c0, ah, bh);                          \
    mma16816(c1, ah, (bh) + 2);                    \
    mma16816(c0, al, bh);                          \
    mma16816(c1, al, (bh) + 2);                    \
    mma16816(c0, ah, bl);                          \
    mma16816(c1, ah, (bl) + 2); } while (0)

// ---------------------------------------------------------------- prep: 4 swizzled weight images
__global__ void k_prep(const float* __restrict__ Wf2, const float* __restrict__ Win,
                       const float* __restrict__ Wo1, const float* __restrict__ Wo2) {
    int idx = blockIdx.x * blockDim.x + threadIdx.x;
    if (idx >= 16384) return;
    int k = idx >> 7, n = idx & 127;
    uint32_t off = (uint32_t)n * 256u + ((uint32_t)((k >> 3) ^ (n & 7)) << 4) + (uint32_t)(k & 7) * 2u;
    {
        float w = Wf2[idx];
        __nv_bfloat16 h = __float2bfloat16(w);
        *(__nv_bfloat16*)(g_W2T[0] + off) = h;
        *(__nv_bfloat16*)(g_W2T[1] + off) = __float2bfloat16(w - __bfloat162float(h));
    }
    {
        float w = Win[idx];
        __nv_bfloat16 h = __float2bfloat16(w);
        *(__nv_bfloat16*)(g_WinT[0] + off) = h;
        *(__nv_bfloat16*)(g_WinT[1] + off) = __float2bfloat16(w - __bfloat162float(h));
    }
    {
        float w = Wo1[idx];
        __nv_bfloat16 h = __float2bfloat16(w);
        *(__nv_bfloat16*)(g_Wo1T[0] + off) = h;
        *(__nv_bfloat16*)(g_Wo1T[1] + off) = __float2bfloat16(w - __bfloat162float(h));
    }
    {
        float w = Wo2[idx];
        __nv_bfloat16 h = __float2bfloat16(w);
        *(__nv_bfloat16*)(g_Wo2T[0] + off) = h;
        *(__nv_bfloat16*)(g_Wo2T[1] + off) = __float2bfloat16(w - __bfloat162float(h));
    }
}

// ---------------------------------------------------------------- zero acc
__global__ void k_zero(int n4) {
    int i = blockIdx.x * blockDim.x + threadIdx.x;
    if (i < n4) reinterpret_cast<float4*>(g_acc)[i] = make_float4(0.f, 0.f, 0.f, 0.f);
}

// ---------------------------------------------------------------- h = x @ W_in (mma bf16-split)
#define SMI_HI 0
#define SMI_LO 32768
#define SMI_TOTAL 65536
__global__ __launch_bounds__(256, 2)
void k_input_mma(const float* __restrict__ x, int N) {
    extern __shared__ char smc[];
    const uint32_t sb = smem_u32(smc);
    const int tid = threadIdx.x, wid = tid >> 5, lane = tid & 31;
    const int l4 = lane >> 2, t2 = (lane & 3) * 2, mi = lane >> 3, l8 = lane & 7;
    {
        const uint4* s0 = (const uint4*)g_WinT[0]; uint4* d0 = (uint4*)(smc + SMI_HI);
        for (int t = tid; t < 2048; t += 256) d0[t] = s0[t];
        const uint4* s1 = (const uint4*)g_WinT[1]; uint4* d1 = (uint4*)(smc + SMI_LO);
        for (int t = tid; t < 2048; t += 256) d1[t] = s1[t];
    }
    __syncthreads();

    const int rA = blockIdx.x * 128 + 16 * wid + l4;
    const bool v0 = rA < N, v1 = rA + 8 < N;
    const uint32_t w2n = (uint32_t)((mi >> 1) * 8 + l8) * 256u;

    float acc[16][4];
#pragma unroll
    for (int b = 0; b < 16; b++)
#pragma unroll
        for (int c = 0; c < 4; c++) acc[b][c] = 0.f;

    const float* x0 = x + (size_t)rA * F;
    const float* x1 = x0 + (size_t)8 * F;
#pragma unroll
    for (int j = 0; j < 8; j++) {
        float2 q0 = make_float2(0.f, 0.f), q1 = q0, q2 = q0, q3 = q0;
        if (v0) { q0 = *(const float2*)(x0 + 16 * j + t2); q2 = *(const float2*)(x0 + 16 * j + t2 + 8); }
        if (v1) { q1 = *(const float2*)(x1 + 16 * j + t2); q3 = *(const float2*)(x1 + 16 * j + t2 + 8); }
        uint32_t ah[4], al[4];
        split_pack(q0.x, q0.y, ah[0], al[0]);
        split_pack(q1.x, q1.y, ah[1], al[1]);
        split_pack(q2.x, q2.y, ah[2], al[2]);
        split_pack(q3.x, q3.y, ah[3], al[3]);
        const uint32_t kb = (uint32_t)(16 * j + (mi & 1) * 8);
        const uint32_t sw = (uint32_t)(((kb >> 3) ^ (uint32_t)l8) << 4);
#pragma unroll
        for (int ng = 0; ng < 8; ng++) {
            uint32_t off = (uint32_t)(16 * ng) * 256u + w2n + sw;
            uint32_t bh[4], bl[4];
            ldsm_x4(bh, sb + SMI_HI + off);
            ldsm_x4(bl, sb + SMI_LO + off);
            MMA6(acc[2 * ng], acc[2 * ng + 1], ah, al, bh, bl);
        }
    }
#pragma unroll
    for (int b = 0; b < 16; b++) {
        int c = 8 * b + t2;
        if (v0) *(float2*)(g_h + (size_t)rA * F + c)       = make_float2(acc[b][0], acc[b][1]);
        if (v1) *(float2*)(g_h + (size_t)(rA + 8) * F + c) = make_float2(acc[b][2], acc[b][3]);
    }
}

// ---------------------------------------------------------------- pair kernel (coalesced epilogue, group-local arenas)
// SMEM: W2hi 32K | W2lo 32K | arena[2] 16K each | bf1 512 | bf2 512
// arena_g (per 4-warp group wm): A2HI-local 8K + A2LO-local 8K; EX (16K) overlays the whole arena.
#define SM_W2HI 0
#define SM_W2LO 32768
#define SM_ARENA 65536          // + wm*16384
#define SM_BF1  98304
#define SM_BF2  98816
#define SM_PAIR_TOTAL 99328

__global__ __launch_bounds__(256, 2)
void k_pairs_mma(const float* __restrict__ f_ij, const float* __restrict__ fcut,
                 const int* __restrict__ pairlist, int P, int ntiles,
                 const float* __restrict__ Wf1,
                 const float* __restrict__ bf1, const float* __restrict__ bf2) {
    extern __shared__ char smc[];
    const uint32_t sb = smem_u32(smc);
    const int tid  = threadIdx.x;
    const int wid  = tid >> 5;
    const int lane = tid & 31;
    const int wm   = wid >> 2;          // 0..1  rows 32*wm (exchange group)
    const int wn   = wid & 3;           // 0..3  cols 32*wn
    const int rbase = 32 * wm;
    const int cbase = 32 * wn;
    const int g  = lane >> 2;
    const int t2 = (lane & 3) * 2;
    const int mi = lane >> 3;
    const int l8 = lane & 7;
    const int barid = 1 + wm;
    const uint32_t arena = SM_ARENA + (uint32_t)wm * 16384u;   // group-local 16KB
    const uint32_t aHI = arena;            // 32 rows x 256B
    const uint32_t aLO = arena + 8192u;    // 32 rows x 256B
    const uint32_t aEX = arena;            // 32 rows x 512B (overlays both)

    {
        const uint4* s0 = (const uint4*)g_W2T[0]; uint4* d0 = (uint4*)(smc + SM_W2HI);
        for (int t = tid; t < 2048; t += 256) d0[t] = s0[t];
        const uint4* s1 = (const uint4*)g_W2T[1]; uint4* d1 = (uint4*)(smc + SM_W2LO);
        for (int t = tid; t < 2048; t += 256) d1[t] = s1[t];
        if (tid < 128) {
            ((float*)(smc + SM_BF1))[tid] = bf1[tid];
            ((float*)(smc + SM_BF2))[tid] = bf2[tid];
        }
    }

    // W1 B-fragments in registers (once)
    uint32_t w1hi[2][2][4], w1lo[2][2][4];
#pragma unroll
    for (int ks = 0; ks < 2; ks++)
#pragma unroll
        for (int ng = 0; ng < 2; ng++)
#pragma unroll
            for (int h = 0; h < 2; h++) {
                int n = cbase + 16 * ng + 8 * h + g;
                int k = 16 * ks + t2;
                float b00 = __ldg(Wf1 + (size_t)k * F + n);
                float b01 = __ldg(Wf1 + (size_t)(k + 1) * F + n);
                float b10 = __ldg(Wf1 + (size_t)(k + 8) * F + n);
                float b11 = __ldg(Wf1 + (size_t)(k + 9) * F + n);
                split_pack(b00, b01, w1hi[ks][ng][2 * h],     w1lo[ks][ng][2 * h]);
                split_pack(b10, b11, w1hi[ks][ng][2 * h + 1], w1lo[ks][ng][2 * h + 1]);
            }

    const float* b1s = (const float*)(smc + SM_BF1);
    const float* b2s = (const float*)(smc + SM_BF2);
    __syncthreads();

    const int l4 = lane >> 2;
    const int l2 = (lane & 3) * 2;

    for (int tile = blockIdx.x; tile < ntiles; tile += gridDim.x) {
        const int p0 = tile * TP;

        float acc[2][4][4];
#pragma unroll
        for (int a = 0; a < 2; a++)
#pragma unroll
            for (int b = 0; b < 4; b++)
#pragma unroll
                for (int c = 0; c < 4; c++) acc[a][b][c] = 0.f;

        // ---- stage 1: S = f_ij @ W1 (K=32), A from gmem ----
#pragma unroll
        for (int ks = 0; ks < 2; ks++) {
            uint32_t ah[2][4], al[2][4];
#pragma unroll
            for (int mt = 0; mt < 2; mt++) {
                int r = p0 + rbase + 16 * mt + g;
                float2 v0 = make_float2(0.f, 0.f), v1 = v0, v2 = v0, v3 = v0;
                if (r < P) {
                    const float* fp = f_ij + (size_t)r * R + 16 * ks + t2;
                    v0 = *(const float2*)fp;
                    v2 = *(const float2*)(fp + 8);
                }
                if (r + 8 < P) {
                    const float* fp = f_ij + (size_t)(r + 8) * R + 16 * ks + t2;
                    v1 = *(const float2*)fp;
                    v3 = *(const float2*)(fp + 8);
                }
                split_pack(v0.x, v0.y, ah[mt][0], al[mt][0]);
                split_pack(v1.x, v1.y, ah[mt][1], al[mt][1]);
                split_pack(v2.x, v2.y, ah[mt][2], al[mt][2]);
                split_pack(v3.x, v3.y, ah[mt][3], al[mt][3]);
            }
#pragma unroll
            for (int ng = 0; ng < 2; ng++)
#pragma unroll
                for (int mt = 0; mt < 2; mt++)
                    MMA6(acc[mt][2 * ng], acc[mt][2 * ng + 1], ah[mt], al[mt],
                         w1hi[ks][ng], w1lo[ks][ng]);
        }

        barn(barid);   // group's previous-tile EX reads done before overwriting arena

        // ---- ssp(S + bf1) -> split -> A2 (group-local, swizzled), reset acc ----
#pragma unroll
        for (int mt = 0; mt < 2; mt++)
#pragma unroll
            for (int nt = 0; nt < 4; nt++) {
                int c = cbase + 8 * nt + l2;
#pragma unroll
                for (int half = 0; half < 2; half++) {
                    int rl = 16 * mt + l4 + 8 * half;          // group-local row 0..31
                    float e0 = sspf(acc[mt][nt][2 * half]     + b1s[c]);
                    float e1 = sspf(acc[mt][nt][2 * half + 1] + b1s[c + 1]);
                    uint32_t hi, lo;
                    split_pack(e0, e1, hi, lo);
                    uint32_t off = (uint32_t)rl * 256u + ((uint32_t)((c >> 3) ^ (rl & 7)) << 4) + (uint32_t)(c & 7) * 2u;
                    *(uint32_t*)(smc + aHI + off) = hi;
                    *(uint32_t*)(smc + aLO + off) = lo;
                }
            }
#pragma unroll
        for (int a = 0; a < 2; a++)
#pragma unroll
            for (int b = 0; b < 4; b++)
#pragma unroll
                for (int c = 0; c < 4; c++) acc[a][b][c] = 0.f;

        barn(barid);   // A2 visible within group

        // ---- stage 2: W_ij = S @ W2 (K=128) ----
#pragma unroll 1
        for (int ks = 0; ks < 8; ks++) {
            const int k0 = ks * 16;
            uint32_t ah[2][4], al[2][4];
#pragma unroll
            for (int mt = 0; mt < 2; mt++) {
                int rl = 16 * mt + (mi & 1) * 8 + l8;          // group-local row
                int kb = k0 + (mi >> 1) * 8;
                uint32_t off = (uint32_t)rl * 256u + ((uint32_t)((kb >> 3) ^ (rl & 7)) << 4);
                ldsm_x4(ah[mt], sb + aHI + off);
                ldsm_x4(al[mt], sb + aLO + off);
            }
#pragma unroll
            for (int ng = 0; ng < 2; ng++) {
                int n  = cbase + 16 * ng + (mi >> 1) * 8 + l8;
                int kb = k0 + (mi & 1) * 8;
                uint32_t off = (uint32_t)n * 256u + ((uint32_t)((kb >> 3) ^ (n & 7)) << 4);
                uint32_t bh[4], bl[4];
                ldsm_x4(bh, sb + SM_W2HI + off);
                ldsm_x4(bl, sb + SM_W2LO + off);
#pragma unroll
                for (int mt = 0; mt < 2; mt++)
                    MMA6(acc[mt][2 * ng], acc[mt][2 * ng + 1], ah[mt], al[mt], bh, bl);
            }
        }

        barn(barid);   // group's stage-2 A2 reads done; EX may overwrite the arena

        // ---- write (W_ij + bf2) to f32 exchange (group-local, XOR-swizzled) ----
#pragma unroll
        for (int mt = 0; mt < 2; mt++)
#pragma unroll
            for (int nt = 0; nt < 4; nt++) {
                int c = cbase + 8 * nt + l2;
#pragma unroll
                for (int half = 0; half < 2; half++) {
                    int rl = 16 * mt + l4 + 8 * half;
                    uint32_t byte = (uint32_t)rl * 512u + (((uint32_t)c * 4u) ^ ((uint32_t)(rl & 7) << 4));
                    *(float2*)(smc + aEX + byte) =
                        make_float2(acc[mt][nt][2 * half] + b2s[c],
                                    acc[mt][nt][2 * half + 1] + b2s[c + 1]);
                }
            }

        barn(barid);   // EX visible within group

        // ---- row phase: warp handles 8 whole rows, fully coalesced ----
        {
            const int rlw = 8 * wn;                            // group-local row base
#pragma unroll
            for (int rr = 0; rr < 8; rr++) {
                const int rl = rlw + rr;
                const int p = p0 + rbase + rl;
                if (p < P) {
                    float cu = __ldg(fcut + p);
                    int ai = __ldg(pairlist + p);
                    int aj = __ldg(pairlist + (size_t)P + p);
                    uint32_t byte = (uint32_t)rl * 512u + (((uint32_t)lane * 16u) ^ ((uint32_t)(rl & 7) << 4));
                    float4 w = *(const float4*)(smc + aEX + byte);
                    float4 hv = __ldg((const float4*)(g_h + (size_t)aj * F + lane * 4));
                    float4 v;
                    v.x = w.x * cu * hv.x;
                    v.y = w.y * cu * hv.y;
                    v.z = w.z * cu * hv.z;
                    v.w = w.w * cu * hv.w;
                    red_add_v4(g_acc + (size_t)ai * F + lane * 4, v);
                }
            }
        }
    }
}

// ---------------------------------------------------------------- out = ssp(acc@Wo1+bo1)@Wo2 + bo2 (mma, register C->A identity)
#define SMO_1HI 0
#define SMO_1LO 32768
#define SMO_2HI 65536
#define SMO_2LO 98304
#define SMO_BO1 131072
#define SMO_BO2 131584
#define SMO_TOTAL 132096
__global__ __launch_bounds__(256, 1)
void k_output_mma(const float* __restrict__ bo1, const float* __restrict__ bo2,
                  float* __restrict__ out, int N) {
    extern __shared__ char smc[];
    const uint32_t sb = smem_u32(smc);
    const int tid = threadIdx.x, wid = tid >> 5, lane = tid & 31;
    const int l4 = lane >> 2, t2 = (lane & 3) * 2, mi = lane >> 3, l8 = lane & 7;
    {
        const uint4* s0 = (const uint4*)g_Wo1T[0]; uint4* d0 = (uint4*)(smc + SMO_1HI);
        for (int t = tid; t < 2048; t += 256) d0[t] = s0[t];
        const uint4* s1 = (const uint4*)g_Wo1T[1]; uint4* d1 = (uint4*)(smc + SMO_1LO);
        for (int t = tid; t < 2048; t += 256) d1[t] = s1[t];
        const uint4* s2 = (const uint4*)g_Wo2T[0]; uint4* d2 = (uint4*)(smc + SMO_2HI);
        for (int t = tid; t < 2048; t += 256) d2[t] = s2[t];
        const uint4* s3 = (const uint4*)g_Wo2T[1]; uint4* d3 = (uint4*)(smc + SMO_2LO);
        for (int t = tid; t < 2048; t += 256) d3[t] = s3[t];
        if (tid < 128) {
            ((float*)(smc + SMO_BO1))[tid] = bo1[tid];
            ((float*)(smc + SMO_BO2))[tid] = bo2[tid];
        }
    }
    __syncthreads();

    const int rA = blockIdx.x * 128 + 16 * wid + l4;
    const bool v0 = rA < N, v1 = rA + 8 < N;
    const uint32_t w2n = (uint32_t)((mi >> 1) * 8 + l8) * 256u;
    const float* b1s = (const float*)(smc + SMO_BO1);
    const float* b2s = (const float*)(smc + SMO_BO2);

    float acc[16][4];
#pragma unroll
    for (int b = 0; b < 16; b++)
#pragma unroll
        for (int c = 0; c < 4; c++) acc[b][c] = 0.f;

    const float* a0 = g_acc + (size_t)rA * F;
    const float* a1 = a0 + (size_t)8 * F;
#pragma unroll
    for (int j = 0; j < 8; j++) {
        float2 q0 = make_float2(0.f, 0.f), q1 = q0, q2 = q0, q3 = q0;
        if (v0) { q0 = *(const float2*)(a0 + 16 * j + t2); q2 = *(const float2*)(a0 + 16 * j + t2 + 8); }
        if (v1) { q1 = *(const float2*)(a1 + 16 * j + t2); q3 = *(const float2*)(a1 + 16 * j + t2 + 8); }
        uint32_t ah[4], al[4];
        split_pack(q0.x, q0.y, ah[0], al[0]);
        split_pack(q1.x, q1.y, ah[1], al[1]);
        split_pack(q2.x, q2.y, ah[2], al[2]);
        split_pack(q3.x, q3.y, ah[3], al[3]);
        const uint32_t kb = (uint32_t)(16 * j + (mi & 1) * 8);
        const uint32_t sw = (uint32_t)(((kb >> 3) ^ (uint32_t)l8) << 4);
#pragma unroll
        for (int ng = 0; ng < 8; ng++) {
            uint32_t off = (uint32_t)(16 * ng) * 256u + w2n + sw;
            uint32_t bh[4], bl[4];
            ldsm_x4(bh, sb + SMO_1HI + off);
            ldsm_x4(bl, sb + SMO_1LO + off);
            MMA6(acc[2 * ng], acc[2 * ng + 1], ah, al, bh, bl);
        }
    }

    uint32_t a2hi[32], a2lo[32];
#pragma unroll
    for (int b = 0; b < 16; b++) {
        int c = 8 * b + t2;
        float e0 = sspf(acc[b][0] + b1s[c]);
        float e1 = sspf(acc[b][1] + b1s[c + 1]);
        float e2 = sspf(acc[b][2] + b1s[c]);
        float e3 = sspf(acc[b][3] + b1s[c + 1]);
        split_pack(e0, e1, a2hi[2 * b],     a2lo[2 * b]);
        split_pack(e2, e3, a2hi[2 * b + 1], a2lo[2 * b + 1]);
#pragma unroll
        for (int q = 0; q < 4; q++) acc[b][q] = 0.f;
    }

#pragma unroll
    for (int j = 0; j < 8; j++) {
        const uint32_t* ahf = a2hi + 4 * j;
        const uint32_t* alf = a2lo + 4 * j;
        const uint32_t kb = (uint32_t)(16 * j + (mi & 1) * 8);
        const uint32_t sw = (uint32_t)(((kb >> 3) ^ (uint32_t)l8) << 4);
#pragma unroll
        for (int ng = 0; ng < 8; ng++) {
            uint32_t off = (uint32_t)(16 * ng) * 256u + w2n + sw;
            uint32_t bh[4], bl[4];
            ldsm_x4(bh, sb + SMO_2HI + off);
            ldsm_x4(bl, sb + SMO_2LO + off);
            MMA6(acc[2 * ng], acc[2 * ng + 1], ahf, alf, bh, bl);
        }
    }

#pragma unroll
    for (int b = 0; b < 16; b++) {
        int c = 8 * b + t2;
        if (v0) *(float2*)(out + (size_t)rA * F + c) =
            make_float2(acc[b][0] + b2s[c], acc[b][1] + b2s[c + 1]);
        if (v1) *(float2*)(out + (size_t)(rA + 8) * F + c) =
            make_float2(acc[b][2] + b2s[c], acc[b][3] + b2s[c + 1]);
    }
}

// ----------------------------------------------------------------- launcher
extern "C" void kernel_launch(void* const* d_in, const int* in_sizes, int n_in,
                              void* d_out, int out_size) {
    const float* x    = (const float*)d_in[0];
    const int*   pl   = (const int*)  d_in[1];
    const float* f_ij = (const float*)d_in[2];
    const float* fcut = (const float*)d_in[3];
    const float* Win  = (const float*)d_in[4];
    const float* Wf1  = (const float*)d_in[5];
    const float* bf1  = (const float*)d_in[6];
    const float* Wf2  = (const float*)d_in[7];
    const float* bf2  = (const float*)d_in[8];
    const float* Wo1  = (const float*)d_in[9];
    const float* bo1  = (const float*)d_in[10];
    const float* Wo2  = (const float*)d_in[11];
    const float* bo2  = (const float*)d_in[12];
    float* out = (float*)d_out;

    const int N = in_sizes[0] / F;
    const int P = in_sizes[1] / 2;
    const int ntiles = (P + TP - 1) / TP;
    const int nrow_tiles = (N + 127) / 128;

    cudaFuncSetAttribute(k_input_mma,  cudaFuncAttributeMaxDynamicSharedMemorySize, SMI_TOTAL);
    cudaFuncSetAttribute(k_pairs_mma,  cudaFuncAttributeMaxDynamicSharedMemorySize, SM_PAIR_TOTAL);
    cudaFuncSetAttribute(k_output_mma, cudaFuncAttributeMaxDynamicSharedMemorySize, SMO_TOTAL);

    const int n4 = N * F / 4;
    k_prep<<<64, 256>>>(Wf2, Win, Wo1, Wo2);
    k_zero<<<(n4 + 255) / 256, 256>>>(n4);
    k_input_mma<<<nrow_tiles, 256, SMI_TOTAL>>>(x, N);
    int grid = ntiles < 296 ? ntiles : 296;
    k_pairs_mma<<<grid, 256, SM_PAIR_TOTAL>>>(f_ij, fcut, pl, P, ntiles, Wf1, bf1, bf2);
    k_output_mma<<<nrow_tiles, 256, SMO_TOTAL>>>(bo1, bo2, out, N);
}

// round 12
// speedup vs baseline: 1.4150x; 1.4150x over previous
#include <cuda_runtime.h>
#include <cuda_bf16.h>
#include <cstdint>
#include <math.h>

#define F   128
#define R   32
#define TP  64       // pairs per tile in k_pairs
#define NT  256

// ---------------------------------------------------------------- scratch
__device__ float g_h  [100000 * 128];
__device__ float g_acc[100000 * 128];
__device__ unsigned char g_W2T [2][32768];  // Wf2^T  [n][k] bf16 hi/lo, 256B rows, XOR-swizzled
__device__ unsigned char g_WinT[2][32768];  // W_in^T
__device__ unsigned char g_Wo1T[2][32768];  // Wo1^T
__device__ unsigned char g_Wo2T[2][32768];  // Wo2^T

// ---------------------------------------------------------------- helpers
__device__ __forceinline__ uint32_t smem_u32(const void* p) {
    uint32_t a;
    asm("{ .reg .u64 t; cvta.to.shared.u64 t, %1; cvt.u32.u64 %0, t; }" : "=r"(a) : "l"(p));
    return a;
}
__device__ __forceinline__ void barn(int id) {          // named barrier, 128 threads
    asm volatile("bar.sync %0, %1;" :: "r"(id), "r"(128) : "memory");
}
__device__ __forceinline__ float sspf(float x) {
    float e = __expf(-fabsf(x));
    return fmaxf(x, 0.0f) + __logf(1.0f + e) - 0.6931471805599453f;
}
__device__ __forceinline__ void red_add_v4(float* p, float4 v) {
    asm volatile("red.global.add.v4.f32 [%0], {%1,%2,%3,%4};"
                 :: "l"(p), "f"(v.x), "f"(v.y), "f"(v.z), "f"(v.w) : "memory");
}
__device__ __forceinline__ void red_add_v2(float* p, float a, float b) {
    asm volatile("red.global.add.v2.f32 [%0], {%1,%2};"
                 :: "l"(p), "f"(a), "f"(b) : "memory");
}
__device__ __forceinline__ void split_pack(float a, float b, uint32_t& hi, uint32_t& lo) {
    __nv_bfloat16 ah = __float2bfloat16(a), bh = __float2bfloat16(b);
    float ar = a - __bfloat162float(ah);
    float br = b - __bfloat162float(bh);
    __nv_bfloat16 al = __float2bfloat16(ar), bl = __float2bfloat16(br);
    hi = ((uint32_t)__bfloat16_as_ushort(bh) << 16) | (uint32_t)__bfloat16_as_ushort(ah);
    lo = ((uint32_t)__bfloat16_as_ushort(bl) << 16) | (uint32_t)__bfloat16_as_ushort(al);
}
__device__ __forceinline__ void mma16816(float* c, const uint32_t* a, const uint32_t* b) {
    asm volatile("mma.sync.aligned.m16n8k16.row.col.f32.bf16.bf16.f32 "
                 "{%0,%1,%2,%3}, {%4,%5,%6,%7}, {%8,%9}, {%0,%1,%2,%3};"
                 : "+f"(c[0]), "+f"(c[1]), "+f"(c[2]), "+f"(c[3])
                 : "r"(a[0]), "r"(a[1]), "r"(a[2]), "r"(a[3]), "r"(b[0]), "r"(b[1]));
}
__device__ __forceinline__ void ldsm_x4(uint32_t* r, uint32_t addr) {
    asm volatile("ldmatrix.sync.aligned.m8n8.x4.shared.b16 {%0,%1,%2,%3}, [%4];"
                 : "=r"(r[0]), "=r"(r[1]), "=r"(r[2]), "=r"(r[3]) : "r"(addr));
}
// interleaved 3-term split MMA: chains c0/c1 alternate (dep distance 2)
#define MMA6(c0, c1, ah, al, bh, bl) do {          \
    mma16816(c0, ah, bh);                          \
    mma16816(c1, ah, (bh) + 2);                    \
    mma16816(c0, al, bh);                          \
    mma16816(c1, al, (bh) + 2);                    \
    mma16816(c0, ah, bl);                          \
    mma16816(c1, ah, (bl) + 2); } while (0)

// ---------------------------------------------------------------- prep: 4 swizzled weight images
__global__ void k_prep(const float* __restrict__ Wf2, const float* __restrict__ Win,
                       const float* __restrict__ Wo1, const float* __restrict__ Wo2) {
    int idx = blockIdx.x * blockDim.x + threadIdx.x;
    if (idx >= 16384) return;
    int k = idx >> 7, n = idx & 127;
    uint32_t off = (uint32_t)n * 256u + ((uint32_t)((k >> 3) ^ (n & 7)) << 4) + (uint32_t)(k & 7) * 2u;
    {
        float w = Wf2[idx];
        __nv_bfloat16 h = __float2bfloat16(w);
        *(__nv_bfloat16*)(g_W2T[0] + off) = h;
        *(__nv_bfloat16*)(g_W2T[1] + off) = __float2bfloat16(w - __bfloat162float(h));
    }
    {
        float w = Win[idx];
        __nv_bfloat16 h = __float2bfloat16(w);
        *(__nv_bfloat16*)(g_WinT[0] + off) = h;
        *(__nv_bfloat16*)(g_WinT[1] + off) = __float2bfloat16(w - __bfloat162float(h));
    }
    {
        float w = Wo1[idx];
        __nv_bfloat16 h = __float2bfloat16(w);
        *(__nv_bfloat16*)(g_Wo1T[0] + off) = h;
        *(__nv_bfloat16*)(g_Wo1T[1] + off) = __float2bfloat16(w - __bfloat162float(h));
    }
    {
        float w = Wo2[idx];
        __nv_bfloat16 h = __float2bfloat16(w);
        *(__nv_bfloat16*)(g_Wo2T[0] + off) = h;
        *(__nv_bfloat16*)(g_Wo2T[1] + off) = __float2bfloat16(w - __bfloat162float(h));
    }
}

// ---------------------------------------------------------------- zero acc
__global__ void k_zero(int n4) {
    int i = blockIdx.x * blockDim.x + threadIdx.x;
    if (i < n4) reinterpret_cast<float4*>(g_acc)[i] = make_float4(0.f, 0.f, 0.f, 0.f);
}

// ---------------------------------------------------------------- h = x @ W_in (mma bf16-split)
#define SMI_HI 0
#define SMI_LO 32768
#define SMI_TOTAL 65536
__global__ __launch_bounds__(256, 2)
void k_input_mma(const float* __restrict__ x, int N) {
    extern __shared__ char smc[];
    const uint32_t sb = smem_u32(smc);
    const int tid = threadIdx.x, wid = tid >> 5, lane = tid & 31;
    const int l4 = lane >> 2, t2 = (lane & 3) * 2, mi = lane >> 3, l8 = lane & 7;
    {
        const uint4* s0 = (const uint4*)g_WinT[0]; uint4* d0 = (uint4*)(smc + SMI_HI);
        for (int t = tid; t < 2048; t += 256) d0[t] = s0[t];
        const uint4* s1 = (const uint4*)g_WinT[1]; uint4* d1 = (uint4*)(smc + SMI_LO);
        for (int t = tid; t < 2048; t += 256) d1[t] = s1[t];
    }
    __syncthreads();

    const int rA = blockIdx.x * 128 + 16 * wid + l4;
    const bool v0 = rA < N, v1 = rA + 8 < N;
    const uint32_t w2n = (uint32_t)((mi >> 1) * 8 + l8) * 256u;

    float acc[16][4];
#pragma unroll
    for (int b = 0; b < 16; b++)
#pragma unroll
        for (int c = 0; c < 4; c++) acc[b][c] = 0.f;

    const float* x0 = x + (size_t)rA * F;
    const float* x1 = x0 + (size_t)8 * F;
#pragma unroll
    for (int j = 0; j < 8; j++) {
        float2 q0 = make_float2(0.f, 0.f), q1 = q0, q2 = q0, q3 = q0;
        if (v0) { q0 = *(const float2*)(x0 + 16 * j + t2); q2 = *(const float2*)(x0 + 16 * j + t2 + 8); }
        if (v1) { q1 = *(const float2*)(x1 + 16 * j + t2); q3 = *(const float2*)(x1 + 16 * j + t2 + 8); }
        uint32_t ah[4], al[4];
        split_pack(q0.x, q0.y, ah[0], al[0]);
        split_pack(q1.x, q1.y, ah[1], al[1]);
        split_pack(q2.x, q2.y, ah[2], al[2]);
        split_pack(q3.x, q3.y, ah[3], al[3]);
        const uint32_t kb = (uint32_t)(16 * j + (mi & 1) * 8);
        const uint32_t sw = (uint32_t)(((kb >> 3) ^ (uint32_t)l8) << 4);
#pragma unroll
        for (int ng = 0; ng < 8; ng++) {
            uint32_t off = (uint32_t)(16 * ng) * 256u + w2n + sw;
            uint32_t bh[4], bl[4];
            ldsm_x4(bh, sb + SMI_HI + off);
            ldsm_x4(bl, sb + SMI_LO + off);
            MMA6(acc[2 * ng], acc[2 * ng + 1], ah, al, bh, bl);
        }
    }
#pragma unroll
    for (int b = 0; b < 16; b++) {
        int c = 8 * b + t2;
        if (v0) *(float2*)(g_h + (size_t)rA * F + c)       = make_float2(acc[b][0], acc[b][1]);
        if (v1) *(float2*)(g_h + (size_t)(rA + 8) * F + c) = make_float2(acc[b][2], acc[b][3]);
    }
}

// ---------------------------------------------------------------- pair kernel (R8 + warp-local coalesced epilogue)
// SMEM: W2hi 32K | W2lo 32K | A2hi 16K | A2lo 16K | WEX 8x1152 | bf1 512 | bf2 512
#define SM_W2HI 0
#define SM_W2LO 32768
#define SM_A2HI 65536
#define SM_A2LO 81920
#define SM_WEX  98304          // per-warp: + wid*1152 (8 rows x 144B)
#define SM_BF1  107520
#define SM_BF2  108032
#define SM_PAIR_TOTAL 108544

__global__ __launch_bounds__(256, 2)
void k_pairs_mma(const float* __restrict__ f_ij, const float* __restrict__ fcut,
                 const int* __restrict__ pairlist, int P, int ntiles,
                 const float* __restrict__ Wf1,
                 const float* __restrict__ bf1, const float* __restrict__ bf2) {
    extern __shared__ char smc[];
    const uint32_t sb = smem_u32(smc);
    const int tid  = threadIdx.x;
    const int wid  = tid >> 5;
    const int lane = tid & 31;
    const int wm   = wid >> 2;          // 0..1  rows 32*wm (exchange group)
    const int wn   = wid & 3;           // 0..3  cols 32*wn
    const int rbase = 32 * wm;
    const int cbase = 32 * wn;
    const int g  = lane >> 2;
    const int t2 = (lane & 3) * 2;
    const int mi = lane >> 3;
    const int l8 = lane & 7;
    const int barid = 1 + wm;
    const uint32_t wex = SM_WEX + (uint32_t)wid * 1152u;

    {
        const uint4* s0 = (const uint4*)g_W2T[0]; uint4* d0 = (uint4*)(smc + SM_W2HI);
        for (int t = tid; t < 2048; t += 256) d0[t] = s0[t];
        const uint4* s1 = (const uint4*)g_W2T[1]; uint4* d1 = (uint4*)(smc + SM_W2LO);
        for (int t = tid; t < 2048; t += 256) d1[t] = s1[t];
        if (tid < 128) {
            ((float*)(smc + SM_BF1))[tid] = bf1[tid];
            ((float*)(smc + SM_BF2))[tid] = bf2[tid];
        }
    }

    // W1 B-fragments in registers (once)
    uint32_t w1hi[2][2][4], w1lo[2][2][4];
#pragma unroll
    for (int ks = 0; ks < 2; ks++)
#pragma unroll
        for (int ng = 0; ng < 2; ng++)
#pragma unroll
            for (int h = 0; h < 2; h++) {
                int n = cbase + 16 * ng + 8 * h + g;
                int k = 16 * ks + t2;
                float b00 = __ldg(Wf1 + (size_t)k * F + n);
                float b01 = __ldg(Wf1 + (size_t)(k + 1) * F + n);
                float b10 = __ldg(Wf1 + (size_t)(k + 8) * F + n);
                float b11 = __ldg(Wf1 + (size_t)(k + 9) * F + n);
                split_pack(b00, b01, w1hi[ks][ng][2 * h],     w1lo[ks][ng][2 * h]);
                split_pack(b10, b11, w1hi[ks][ng][2 * h + 1], w1lo[ks][ng][2 * h + 1]);
            }

    const float* b1s = (const float*)(smc + SM_BF1);
    const float* b2s = (const float*)(smc + SM_BF2);
    __syncthreads();

    const int l4 = lane >> 2;
    const int l2 = (lane & 3) * 2;

    for (int tile = blockIdx.x; tile < ntiles; tile += gridDim.x) {
        const int p0 = tile * TP;

        // per-tile metadata: lane = warp-local row (32 rows), coalesced loads + shfl later
        float m_cut = 0.f; int m_ai = 0, m_aj = 0;
        {
            int pm = p0 + rbase + lane;
            if (pm < P) {
                m_cut = __ldg(fcut + pm);
                m_ai  = __ldg(pairlist + pm);
                m_aj  = __ldg(pairlist + (size_t)P + pm);
            }
        }

        float acc[2][4][4];
#pragma unroll
        for (int a = 0; a < 2; a++)
#pragma unroll
            for (int b = 0; b < 4; b++)
#pragma unroll
                for (int c = 0; c < 4; c++) acc[a][b][c] = 0.f;

        // ---- stage 1: S = f_ij @ W1 (K=32), A from gmem ----
#pragma unroll
        for (int ks = 0; ks < 2; ks++) {
            uint32_t ah[2][4], al[2][4];
#pragma unroll
            for (int mt = 0; mt < 2; mt++) {
                int r = p0 + rbase + 16 * mt + g;
                float2 v0 = make_float2(0.f, 0.f), v1 = v0, v2 = v0, v3 = v0;
                if (r < P) {
                    const float* fp = f_ij + (size_t)r * R + 16 * ks + t2;
                    v0 = *(const float2*)fp;
                    v2 = *(const float2*)(fp + 8);
                }
                if (r + 8 < P) {
                    const float* fp = f_ij + (size_t)(r + 8) * R + 16 * ks + t2;
                    v1 = *(const float2*)fp;
                    v3 = *(const float2*)(fp + 8);
                }
                split_pack(v0.x, v0.y, ah[mt][0], al[mt][0]);
                split_pack(v1.x, v1.y, ah[mt][1], al[mt][1]);
                split_pack(v2.x, v2.y, ah[mt][2], al[mt][2]);
                split_pack(v3.x, v3.y, ah[mt][3], al[mt][3]);
            }
#pragma unroll
            for (int ng = 0; ng < 2; ng++)
#pragma unroll
                for (int mt = 0; mt < 2; mt++)
                    MMA6(acc[mt][2 * ng], acc[mt][2 * ng + 1], ah[mt], al[mt],
                         w1hi[ks][ng], w1lo[ks][ng]);
        }

        barn(barid);   // group's previous-tile stage-2 reads of A2 done

        // ---- ssp(S + bf1) -> split -> A2 smem (swizzled), reset acc ----
#pragma unroll
        for (int mt = 0; mt < 2; mt++)
#pragma unroll
            for (int nt = 0; nt < 4; nt++) {
                int c = cbase + 8 * nt + l2;
#pragma unroll
                for (int half = 0; half < 2; half++) {
                    int r = rbase + 16 * mt + l4 + 8 * half;
                    float e0 = sspf(acc[mt][nt][2 * half]     + b1s[c]);
                    float e1 = sspf(acc[mt][nt][2 * half + 1] + b1s[c + 1]);
                    uint32_t hi, lo;
                    split_pack(e0, e1, hi, lo);
                    uint32_t off = (uint32_t)r * 256u + ((uint32_t)((c >> 3) ^ (r & 7)) << 4) + (uint32_t)(c & 7) * 2u;
                    *(uint32_t*)(smc + SM_A2HI + off) = hi;
                    *(uint32_t*)(smc + SM_A2LO + off) = lo;
                }
            }
#pragma unroll
        for (int a = 0; a < 2; a++)
#pragma unroll
            for (int b = 0; b < 4; b++)
#pragma unroll
                for (int c = 0; c < 4; c++) acc[a][b][c] = 0.f;

        barn(barid);   // A2 visible within group

        // ---- stage 2: W_ij = S @ W2 (K=128) ----
#pragma unroll 1
        for (int ks = 0; ks < 8; ks++) {
            const int k0 = ks * 16;
            uint32_t ah[2][4], al[2][4];
#pragma unroll
            for (int mt = 0; mt < 2; mt++) {
                int r  = rbase + 16 * mt + (mi & 1) * 8 + l8;
                int kb = k0 + (mi >> 1) * 8;
                uint32_t off = (uint32_t)r * 256u + ((uint32_t)((kb >> 3) ^ (r & 7)) << 4);
                ldsm_x4(ah[mt], sb + SM_A2HI + off);
                ldsm_x4(al[mt], sb + SM_A2LO + off);
            }
#pragma unroll
            for (int ng = 0; ng < 2; ng++) {
                int n  = cbase + 16 * ng + (mi >> 1) * 8 + l8;
                int kb = k0 + (mi & 1) * 8;
                uint32_t off = (uint32_t)n * 256u + ((uint32_t)((kb >> 3) ^ (n & 7)) << 4);
                uint32_t bh[4], bl[4];
                ldsm_x4(bh, sb + SM_W2HI + off);
                ldsm_x4(bl, sb + SM_W2LO + off);
#pragma unroll
                for (int mt = 0; mt < 2; mt++)
                    MMA6(acc[mt][2 * ng], acc[mt][2 * ng + 1], ah[mt], al[mt], bh, bl);
            }
        }

        // ---- epilogue: warp-local smem transpose -> coalesced gather/scatter ----
#pragma unroll
        for (int mt = 0; mt < 2; mt++)
#pragma unroll
            for (int half = 0; half < 2; half++) {
                __syncwarp();    // prior pass LDS reads complete before overwriting WEX
#pragma unroll
                for (int nt = 0; nt < 4; nt++) {
                    int c = cbase + 8 * nt + l2;
                    uint32_t off = (uint32_t)l4 * 144u + (uint32_t)(8 * nt + l2) * 4u;
                    *(float2*)(smc + wex + off) =
                        make_float2(acc[mt][nt][2 * half] + b2s[c],
                                    acc[mt][nt][2 * half + 1] + b2s[c + 1]);
                }
                __syncwarp();    // WEX visible within warp
#pragma unroll
                for (int it = 0; it < 2; it++) {
                    int rl  = it * 4 + (lane >> 3);         // 0..7 row slot
                    int idx = 16 * mt + 8 * half + rl;      // warp-local row 0..31
                    float cu = __shfl_sync(0xffffffffu, m_cut, idx);
                    int   ai = __shfl_sync(0xffffffffu, m_ai,  idx);
                    int   aj = __shfl_sync(0xffffffffu, m_aj,  idx);
                    int p = p0 + rbase + idx;
                    if (p < P) {
                        int q = lane & 7;
                        float4 w = *(const float4*)(smc + wex + (uint32_t)rl * 144u + (uint32_t)q * 16u);
                        float4 hv = __ldg((const float4*)(g_h + (size_t)aj * F + cbase + q * 4));
                        float4 v;
                        v.x = w.x * cu * hv.x;
                        v.y = w.y * cu * hv.y;
                        v.z = w.z * cu * hv.z;
                        v.w = w.w * cu * hv.w;
                        red_add_v4(g_acc + (size_t)ai * F + cbase + q * 4, v);
                    }
                }
            }
    }
}

// ---------------------------------------------------------------- out = ssp(acc@Wo1+bo1)@Wo2 + bo2 (mma, register C->A identity)
#define SMO_1HI 0
#define SMO_1LO 32768
#define SMO_2HI 65536
#define SMO_2LO 98304
#define SMO_BO1 131072
#define SMO_BO2 131584
#define SMO_TOTAL 132096
__global__ __launch_bounds__(256, 1)
void k_output_mma(const float* __restrict__ bo1, const float* __restrict__ bo2,
                  float* __restrict__ out, int N) {
    extern __shared__ char smc[];
    const uint32_t sb = smem_u32(smc);
    const int tid = threadIdx.x, wid = tid >> 5, lane = tid & 31;
    const int l4 = lane >> 2, t2 = (lane & 3) * 2, mi = lane >> 3, l8 = lane & 7;
    {
        const uint4* s0 = (const uint4*)g_Wo1T[0]; uint4* d0 = (uint4*)(smc + SMO_1HI);
        for (int t = tid; t < 2048; t += 256) d0[t] = s0[t];
        const uint4* s1 = (const uint4*)g_Wo1T[1]; uint4* d1 = (uint4*)(smc + SMO_1LO);
        for (int t = tid; t < 2048; t += 256) d1[t] = s1[t];
        const uint4* s2 = (const uint4*)g_Wo2T[0]; uint4* d2 = (uint4*)(smc + SMO_2HI);
        for (int t = tid; t < 2048; t += 256) d2[t] = s2[t];
        const uint4* s3 = (const uint4*)g_Wo2T[1]; uint4* d3 = (uint4*)(smc + SMO_2LO);
        for (int t = tid; t < 2048; t += 256) d3[t] = s3[t];
        if (tid < 128) {
            ((float*)(smc + SMO_BO1))[tid] = bo1[tid];
            ((float*)(smc + SMO_BO2))[tid] = bo2[tid];
        }
    }
    __syncthreads();

    const int rA = blockIdx.x * 128 + 16 * wid + l4;
    const bool v0 = rA < N, v1 = rA + 8 < N;
    const uint32_t w2n = (uint32_t)((mi >> 1) * 8 + l8) * 256u;
    const float* b1s = (const float*)(smc + SMO_BO1);
    const float* b2s = (const float*)(smc + SMO_BO2);

    float acc[16][4];
#pragma unroll
    for (int b = 0; b < 16; b++)
#pragma unroll
        for (int c = 0; c < 4; c++) acc[b][c] = 0.f;

    const float* a0 = g_acc + (size_t)rA * F;
    const float* a1 = a0 + (size_t)8 * F;
#pragma unroll
    for (int j = 0; j < 8; j++) {
        float2 q0 = make_float2(0.f, 0.f), q1 = q0, q2 = q0, q3 = q0;
        if (v0) { q0 = *(const float2*)(a0 + 16 * j + t2); q2 = *(const float2*)(a0 + 16 * j + t2 + 8); }
        if (v1) { q1 = *(const float2*)(a1 + 16 * j + t2); q3 = *(const float2*)(a1 + 16 * j + t2 + 8); }
        uint32_t ah[4], al[4];
        split_pack(q0.x, q0.y, ah[0], al[0]);
        split_pack(q1.x, q1.y, ah[1], al[1]);
        split_pack(q2.x, q2.y, ah[2], al[2]);
        split_pack(q3.x, q3.y, ah[3], al[3]);
        const uint32_t kb = (uint32_t)(16 * j + (mi & 1) * 8);
        const uint32_t sw = (uint32_t)(((kb >> 3) ^ (uint32_t)l8) << 4);
#pragma unroll
        for (int ng = 0; ng < 8; ng++) {
            uint32_t off = (uint32_t)(16 * ng) * 256u + w2n + sw;
            uint32_t bh[4], bl[4];
            ldsm_x4(bh, sb + SMO_1HI + off);
            ldsm_x4(bl, sb + SMO_1LO + off);
            MMA6(acc[2 * ng], acc[2 * ng + 1], ah, al, bh, bl);
        }
    }

    uint32_t a2hi[32], a2lo[32];
#pragma unroll
    for (int b = 0; b < 16; b++) {
        int c = 8 * b + t2;
        float e0 = sspf(acc[b][0] + b1s[c]);
        float e1 = sspf(acc[b][1] + b1s[c + 1]);
        float e2 = sspf(acc[b][2] + b1s[c]);
        float e3 = sspf(acc[b][3] + b1s[c + 1]);
        split_pack(e0, e1, a2hi[2 * b],     a2lo[2 * b]);
        split_pack(e2, e3, a2hi[2 * b + 1], a2lo[2 * b + 1]);
#pragma unroll
        for (int q = 0; q < 4; q++) acc[b][q] = 0.f;
    }

#pragma unroll
    for (int j = 0; j < 8; j++) {
        const uint32_t* ahf = a2hi + 4 * j;
        const uint32_t* alf = a2lo + 4 * j;
        const uint32_t kb = (uint32_t)(16 * j + (mi & 1) * 8);
        const uint32_t sw = (uint32_t)(((kb >> 3) ^ (uint32_t)l8) << 4);
#pragma unroll
        for (int ng = 0; ng < 8; ng++) {
            uint32_t off = (uint32_t)(16 * ng) * 256u + w2n + sw;
            uint32_t bh[4], bl[4];
            ldsm_x4(bh, sb + SMO_2HI + off);
            ldsm_x4(bl, sb + SMO_2LO + off);
            MMA6(acc[2 * ng], acc[2 * ng + 1], ahf, alf, bh, bl);
        }
    }

#pragma unroll
    for (int b = 0; b < 16; b++) {
        int c = 8 * b + t2;
        if (v0) *(float2*)(out + (size_t)rA * F + c) =
            make_float2(acc[b][0] + b2s[c], acc[b][1] + b2s[c + 1]);
        if (v1) *(float2*)(out + (size_t)(rA + 8) * F + c) =
            make_float2(acc[b][2] + b2s[c], acc[b][3] + b2s[c + 1]);
    }
}

// ----------------------------------------------------------------- launcher
extern "C" void kernel_launch(void* const* d_in, const int* in_sizes, int n_in,
                              void* d_out, int out_size) {
    const float* x    = (const float*)d_in[0];
    const int*   pl   = (const int*)  d_in[1];
    const float* f_ij = (const float*)d_in[2];
    const float* fcut = (const float*)d_in[3];
    const float* Win  = (const float*)d_in[4];
    const float* Wf1  = (const float*)d_in[5];
    const float* bf1  = (const float*)d_in[6];
    const float* Wf2  = (const float*)d_in[7];
    const float* bf2  = (const float*)d_in[8];
    const float* Wo1  = (const float*)d_in[9];
    const float* bo1  = (const float*)d_in[10];
    const float* Wo2  = (const float*)d_in[11];
    const float* bo2  = (const float*)d_in[12];
    float* out = (float*)d_out;

    const int N = in_sizes[0] / F;
    const int P = in_sizes[1] / 2;
    const int ntiles = (P + TP - 1) / TP;
    const int nrow_tiles = (N + 127) / 128;

    cudaFuncSetAttribute(k_input_mma,  cudaFuncAttributeMaxDynamicSharedMemorySize, SMI_TOTAL);
    cudaFuncSetAttribute(k_pairs_mma,  cudaFuncAttributeMaxDynamicSharedMemorySize, SM_PAIR_TOTAL);
    cudaFuncSetAttribute(k_output_mma, cudaFuncAttributeMaxDynamicSharedMemorySize, SMO_TOTAL);

    const int n4 = N * F / 4;
    k_prep<<<64, 256>>>(Wf2, Win, Wo1, Wo2);
    k_zero<<<(n4 + 255) / 256, 256>>>(n4);
    k_input_mma<<<nrow_tiles, 256, SMI_TOTAL>>>(x, N);
    int grid = ntiles < 296 ? ntiles : 296;
    k_pairs_mma<<<grid, 256, SM_PAIR_TOTAL>>>(f_ij, fcut, pl, P, ntiles, Wf1, bf1, bf2);
    k_output_mma<<<nrow_tiles, 256, SMO_TOTAL>>>(bo1, bo2, out, N);
}

// round 15
// speedup vs baseline: 1.4468x; 1.0225x over previous
#include <cuda_runtime.h>
#include <cuda_bf16.h>
#include <cstdint>
#include <math.h>

#define F   128
#define R   32
#define TP  64       // pairs per tile in k_pairs
#define NT  256

// ---------------------------------------------------------------- scratch
__device__ float g_h  [100000 * 128];
__device__ float g_acc[100000 * 128];
__device__ unsigned char g_W2T [2][32768];  // Wf2^T  [n][k] bf16 hi/lo, 256B rows, XOR-swizzled
__device__ unsigned char g_WinT[2][32768];  // W_in^T
__device__ unsigned char g_Wo1T[2][32768];  // Wo1^T
__device__ unsigned char g_Wo2T[2][32768];  // Wo2^T

// ---------------------------------------------------------------- helpers
__device__ __forceinline__ uint32_t smem_u32(const void* p) {
    uint32_t a;
    asm("{ .reg .u64 t; cvta.to.shared.u64 t, %1; cvt.u32.u64 %0, t; }" : "=r"(a) : "l"(p));
    return a;
}
__device__ __forceinline__ void barn(int id) {          // named barrier, 128 threads
    asm volatile("bar.sync %0, %1;" :: "r"(id), "r"(128) : "memory");
}
__device__ __forceinline__ float sspf(float x) {
    float e = __expf(-fabsf(x));
    return fmaxf(x, 0.0f) + __logf(1.0f + e) - 0.6931471805599453f;
}
__device__ __forceinline__ void red_add_v4(float* p, float4 v) {
    asm volatile("red.global.add.v4.f32 [%0], {%1,%2,%3,%4};"
                 :: "l"(p), "f"(v.x), "f"(v.y), "f"(v.z), "f"(v.w) : "memory");
}
__device__ __forceinline__ void split_pack(float a, float b, uint32_t& hi, uint32_t& lo) {
    __nv_bfloat16 ah = __float2bfloat16(a), bh = __float2bfloat16(b);
    float ar = a - __bfloat162float(ah);
    float br = b - __bfloat162float(bh);
    __nv_bfloat16 al = __float2bfloat16(ar), bl = __float2bfloat16(br);
    hi = ((uint32_t)__bfloat16_as_ushort(bh) << 16) | (uint32_t)__bfloat16_as_ushort(ah);
    lo = ((uint32_t)__bfloat16_as_ushort(bl) << 16) | (uint32_t)__bfloat16_as_ushort(al);
}
__device__ __forceinline__ void mma16816(float* c, const uint32_t* a, const uint32_t* b) {
    asm volatile("mma.sync.aligned.m16n8k16.row.col.f32.bf16.bf16.f32 "
                 "{%0,%1,%2,%3}, {%4,%5,%6,%7}, {%8,%9}, {%0,%1,%2,%3};"
                 : "+f"(c[0]), "+f"(c[1]), "+f"(c[2]), "+f"(c[3])
                 : "r"(a[0]), "r"(a[1]), "r"(a[2]), "r"(a[3]), "r"(b[0]), "r"(b[1]));
}
__device__ __forceinline__ void ldsm_x4(uint32_t* r, uint32_t addr) {
    asm volatile("ldmatrix.sync.aligned.m8n8.x4.shared.b16 {%0,%1,%2,%3}, [%4];"
                 : "=r"(r[0]), "=r"(r[1]), "=r"(r[2]), "=r"(r[3]) : "r"(addr));
}
// interleaved 3-term split MMA: chains c0/c1 alternate (dep distance 2)
#define MMA6(c0, c1, ah, al, bh, bl) do {          \
    mma16816(c0, ah, bh);                          \
    mma16816(c1, ah, (bh) + 2);                    \
    mma16816(c0, al, bh);                          \
    mma16816(c1, al, (bh) + 2);                    \
    mma16816(c0, ah, bl);                          \
    mma16816(c1, ah, (bl) + 2); } while (0)

// ---------------------------------------------------------------- prep: weight images + zero g_acc
__global__ void k_prep(const float* __restrict__ Wf2, const float* __restrict__ Win,
                       const float* __restrict__ Wo1, const float* __restrict__ Wo2,
                       int n4) {
    int idx = blockIdx.x * blockDim.x + threadIdx.x;
    if (idx < 16384) {
        int k = idx >> 7, n = idx & 127;
        uint32_t off = (uint32_t)n * 256u + ((uint32_t)((k >> 3) ^ (n & 7)) << 4) + (uint32_t)(k & 7) * 2u;
        {
            float w = Wf2[idx];
            __nv_bfloat16 h = __float2bfloat16(w);
            *(__nv_bfloat16*)(g_W2T[0] + off) = h;
            *(__nv_bfloat16*)(g_W2T[1] + off) = __float2bfloat16(w - __bfloat162float(h));
        }
        {
            float w = Win[idx];
            __nv_bfloat16 h = __float2bfloat16(w);
            *(__nv_bfloat16*)(g_WinT[0] + off) = h;
            *(__nv_bfloat16*)(g_WinT[1] + off) = __float2bfloat16(w - __bfloat162float(h));
        }
        {
            float w = Wo1[idx];
            __nv_bfloat16 h = __float2bfloat16(w);
            *(__nv_bfloat16*)(g_Wo1T[0] + off) = h;
            *(__nv_bfloat16*)(g_Wo1T[1] + off) = __float2bfloat16(w - __bfloat162float(h));
        }
        {
            float w = Wo2[idx];
            __nv_bfloat16 h = __float2bfloat16(w);
            *(__nv_bfloat16*)(g_Wo2T[0] + off) = h;
            *(__nv_bfloat16*)(g_Wo2T[1] + off) = __float2bfloat16(w - __bfloat162float(h));
        }
    }
    // zero segment-sum accumulator (grid-stride)
    const int stride = gridDim.x * blockDim.x;
    for (int i = idx; i < n4; i += stride)
        reinterpret_cast<float4*>(g_acc)[i] = make_float4(0.f, 0.f, 0.f, 0.f);
}

// ---------------------------------------------------------------- h = x @ W_in (mma bf16-split)
#define SMI_HI 0
#define SMI_LO 32768
#define SMI_TOTAL 65536
__global__ __launch_bounds__(256, 2)
void k_input_mma(const float* __restrict__ x, int N) {
    extern __shared__ char smc[];
    const uint32_t sb = smem_u32(smc);
    const int tid = threadIdx.x, wid = tid >> 5, lane = tid & 31;
    const int l4 = lane >> 2, t2 = (lane & 3) * 2, mi = lane >> 3, l8 = lane & 7;
    {
        const uint4* s0 = (const uint4*)g_WinT[0]; uint4* d0 = (uint4*)(smc + SMI_HI);
        for (int t = tid; t < 2048; t += 256) d0[t] = s0[t];
        const uint4* s1 = (const uint4*)g_WinT[1]; uint4* d1 = (uint4*)(smc + SMI_LO);
        for (int t = tid; t < 2048; t += 256) d1[t] = s1[t];
    }
    __syncthreads();

    const int rA = blockIdx.x * 128 + 16 * wid + l4;
    const bool v0 = rA < N, v1 = rA + 8 < N;
    const uint32_t w2n = (uint32_t)((mi >> 1) * 8 + l8) * 256u;

    float acc[16][4];
#pragma unroll
    for (int b = 0; b < 16; b++)
#pragma unroll
        for (int c = 0; c < 4; c++) acc[b][c] = 0.f;

    const float* x0 = x + (size_t)rA * F;
    const float* x1 = x0 + (size_t)8 * F;
#pragma unroll
    for (int j = 0; j < 8; j++) {
        float2 q0 = make_float2(0.f, 0.f), q1 = q0, q2 = q0, q3 = q0;
        if (v0) { q0 = *(const float2*)(x0 + 16 * j + t2); q2 = *(const float2*)(x0 + 16 * j + t2 + 8); }
        if (v1) { q1 = *(const float2*)(x1 + 16 * j + t2); q3 = *(const float2*)(x1 + 16 * j + t2 + 8); }
        uint32_t ah[4], al[4];
        split_pack(q0.x, q0.y, ah[0], al[0]);
        split_pack(q1.x, q1.y, ah[1], al[1]);
        split_pack(q2.x, q2.y, ah[2], al[2]);
        split_pack(q3.x, q3.y, ah[3], al[3]);
        const uint32_t kb = (uint32_t)(16 * j + (mi & 1) * 8);
        const uint32_t sw = (uint32_t)(((kb >> 3) ^ (uint32_t)l8) << 4);
#pragma unroll
        for (int ng = 0; ng < 8; ng++) {
            uint32_t off = (uint32_t)(16 * ng) * 256u + w2n + sw;
            uint32_t bh[4], bl[4];
            ldsm_x4(bh, sb + SMI_HI + off);
            ldsm_x4(bl, sb + SMI_LO + off);
            MMA6(acc[2 * ng], acc[2 * ng + 1], ah, al, bh, bl);
        }
    }
#pragma unroll
    for (int b = 0; b < 16; b++) {
        int c = 8 * b + t2;
        if (v0) *(float2*)(g_h + (size_t)rA * F + c)       = make_float2(acc[b][0], acc[b][1]);
        if (v1) *(float2*)(g_h + (size_t)(rA + 8) * F + c) = make_float2(acc[b][2], acc[b][3]);
    }
}

// ---------------------------------------------------------------- pair kernel (R12 + stage-2 unroll 2)
// SMEM: W2hi 32K | W2lo 32K | A2hi 16K | A2lo 16K | WEX 8x1152 | bf1 512 | bf2 512
#define SM_W2HI 0
#define SM_W2LO 32768
#define SM_A2HI 65536
#define SM_A2LO 81920
#define SM_WEX  98304          // per-warp: + wid*1152 (8 rows x 144B)
#define SM_BF1  107520
#define SM_BF2  108032
#define SM_PAIR_TOTAL 108544

__global__ __launch_bounds__(256, 2)
void k_pairs_mma(const float* __restrict__ f_ij, const float* __restrict__ fcut,
                 const int* __restrict__ pairlist, int P, int ntiles,
                 const float* __restrict__ Wf1,
                 const float* __restrict__ bf1, const float* __restrict__ bf2) {
    extern __shared__ char smc[];
    const uint32_t sb = smem_u32(smc);
    const int tid  = threadIdx.x;
    const int wid  = tid >> 5;
    const int lane = tid & 31;
    const int wm   = wid >> 2;          // 0..1  rows 32*wm (exchange group)
    const int wn   = wid & 3;           // 0..3  cols 32*wn
    const int rbase = 32 * wm;
    const int cbase = 32 * wn;
    const int g  = lane >> 2;
    const int t2 = (lane & 3) * 2;
    const int mi = lane >> 3;
    const int l8 = lane & 7;
    const int barid = 1 + wm;
    const uint32_t wex = SM_WEX + (uint32_t)wid * 1152u;

    {
        const uint4* s0 = (const uint4*)g_W2T[0]; uint4* d0 = (uint4*)(smc + SM_W2HI);
        for (int t = tid; t < 2048; t += 256) d0[t] = s0[t];
        const uint4* s1 = (const uint4*)g_W2T[1]; uint4* d1 = (uint4*)(smc + SM_W2LO);
        for (int t = tid; t < 2048; t += 256) d1[t] = s1[t];
        if (tid < 128) {
            ((float*)(smc + SM_BF1))[tid] = bf1[tid];
            ((float*)(smc + SM_BF2))[tid] = bf2[tid];
        }
    }

    // W1 B-fragments in registers (once)
    uint32_t w1hi[2][2][4], w1lo[2][2][4];
#pragma unroll
    for (int ks = 0; ks < 2; ks++)
#pragma unroll
        for (int ng = 0; ng < 2; ng++)
#pragma unroll
            for (int h = 0; h < 2; h++) {
                int n = cbase + 16 * ng + 8 * h + g;
                int k = 16 * ks + t2;
                float b00 = __ldg(Wf1 + (size_t)k * F + n);
                float b01 = __ldg(Wf1 + (size_t)(k + 1) * F + n);
                float b10 = __ldg(Wf1 + (size_t)(k + 8) * F + n);
                float b11 = __ldg(Wf1 + (size_t)(k + 9) * F + n);
                split_pack(b00, b01, w1hi[ks][ng][2 * h],     w1lo[ks][ng][2 * h]);
                split_pack(b10, b11, w1hi[ks][ng][2 * h + 1], w1lo[ks][ng][2 * h + 1]);
            }

    const float* b1s = (const float*)(smc + SM_BF1);
    const float* b2s = (const float*)(smc + SM_BF2);
    __syncthreads();

    const int l4 = lane >> 2;
    const int l2 = (lane & 3) * 2;

    for (int tile = blockIdx.x; tile < ntiles; tile += gridDim.x) {
        const int p0 = tile * TP;

        // per-tile metadata: lane = warp-local row (32 rows), coalesced loads + shfl later
        float m_cut = 0.f; int m_ai = 0, m_aj = 0;
        {
            int pm = p0 + rbase + lane;
            if (pm < P) {
                m_cut = __ldg(fcut + pm);
                m_ai  = __ldg(pairlist + pm);
                m_aj  = __ldg(pairlist + (size_t)P + pm);
            }
        }

        float acc[2][4][4];
#pragma unroll
        for (int a = 0; a < 2; a++)
#pragma unroll
            for (int b = 0; b < 4; b++)
#pragma unroll
                for (int c = 0; c < 4; c++) acc[a][b][c] = 0.f;

        // ---- stage 1: S = f_ij @ W1 (K=32), A from gmem ----
#pragma unroll
        for (int ks = 0; ks < 2; ks++) {
            uint32_t ah[2][4], al[2][4];
#pragma unroll
            for (int mt = 0; mt < 2; mt++) {
                int r = p0 + rbase + 16 * mt + g;
                float2 v0 = make_float2(0.f, 0.f), v1 = v0, v2 = v0, v3 = v0;
                if (r < P) {
                    const float* fp = f_ij + (size_t)r * R + 16 * ks + t2;
                    v0 = *(const float2*)fp;
                    v2 = *(const float2*)(fp + 8);
                }
                if (r + 8 < P) {
                    const float* fp = f_ij + (size_t)(r + 8) * R + 16 * ks + t2;
                    v1 = *(const float2*)fp;
                    v3 = *(const float2*)(fp + 8);
                }
                split_pack(v0.x, v0.y, ah[mt][0], al[mt][0]);
                split_pack(v1.x, v1.y, ah[mt][1], al[mt][1]);
                split_pack(v2.x, v2.y, ah[mt][2], al[mt][2]);
                split_pack(v3.x, v3.y, ah[mt][3], al[mt][3]);
            }
#pragma unroll
            for (int ng = 0; ng < 2; ng++)
#pragma unroll
                for (int mt = 0; mt < 2; mt++)
                    MMA6(acc[mt][2 * ng], acc[mt][2 * ng + 1], ah[mt], al[mt],
                         w1hi[ks][ng], w1lo[ks][ng]);
        }

        barn(barid);   // group's previous-tile stage-2 reads of A2 done

        // ---- ssp(S + bf1) -> split -> A2 smem (swizzled), reset acc ----
#pragma unroll
        for (int mt = 0; mt < 2; mt++)
#pragma unroll
            for (int nt = 0; nt < 4; nt++) {
                int c = cbase + 8 * nt + l2;
#pragma unroll
                for (int half = 0; half < 2; half++) {
                    int r = rbase + 16 * mt + l4 + 8 * half;
                    float e0 = sspf(acc[mt][nt][2 * half]     + b1s[c]);
                    float e1 = sspf(acc[mt][nt][2 * half + 1] + b1s[c + 1]);
                    uint32_t hi, lo;
                    split_pack(e0, e1, hi, lo);
                    uint32_t off = (uint32_t)r * 256u + ((uint32_t)((c >> 3) ^ (r & 7)) << 4) + (uint32_t)(c & 7) * 2u;
                    *(uint32_t*)(smc + SM_A2HI + off) = hi;
                    *(uint32_t*)(smc + SM_A2LO + off) = lo;
                }
            }
#pragma unroll
        for (int a = 0; a < 2; a++)
#pragma unroll
            for (int b = 0; b < 4; b++)
#pragma unroll
                for (int c = 0; c < 4; c++) acc[a][b][c] = 0.f;

        barn(barid);   // A2 visible within group

        // ---- stage 2: W_ij = S @ W2 (K=128), unroll 2 for load/mma overlap ----
#pragma unroll 2
        for (int ks = 0; ks < 8; ks++) {
            const int k0 = ks * 16;
            uint32_t ah[2][4], al[2][4];
#pragma unroll
            for (int mt = 0; mt < 2; mt++) {
                int r  = rbase + 16 * mt + (mi & 1) * 8 + l8;
                int kb = k0 + (mi >> 1) * 8;
                uint32_t off = (uint32_t)r * 256u + ((uint32_t)((kb >> 3) ^ (r & 7)) << 4);
                ldsm_x4(ah[mt], sb + SM_A2HI + off);
                ldsm_x4(al[mt], sb + SM_A2LO + off);
            }
#pragma unroll
            for (int ng = 0; ng < 2; ng++) {
                int n  = cbase + 16 * ng + (mi >> 1) * 8 + l8;
                int kb = k0 + (mi & 1) * 8;
                uint32_t off = (uint32_t)n * 256u + ((uint32_t)((kb >> 3) ^ (n & 7)) << 4);
                uint32_t bh[4], bl[4];
                ldsm_x4(bh, sb + SM_W2HI + off);
                ldsm_x4(bl, sb + SM_W2LO + off);
#pragma unroll
                for (int mt = 0; mt < 2; mt++)
                    MMA6(acc[mt][2 * ng], acc[mt][2 * ng + 1], ah[mt], al[mt], bh, bl);
            }
        }

        // ---- epilogue: warp-local smem transpose -> coalesced gather/scatter ----
#pragma unroll
        for (int mt = 0; mt < 2; mt++)
#pragma unroll
            for (int half = 0; half < 2; half++) {
                __syncwarp();    // prior pass LDS reads complete before overwriting WEX
#pragma unroll
                for (int nt = 0; nt < 4; nt++) {
                    int c = cbase + 8 * nt + l2;
                    uint32_t off = (uint32_t)l4 * 144u + (uint32_t)(8 * nt + l2) * 4u;
                    *(float2*)(smc + wex + off) =
                        make_float2(acc[mt][nt][2 * half] + b2s[c],
                                    acc[mt][nt][2 * half + 1] + b2s[c + 1]);
                }
                __syncwarp();    // WEX visible within warp
#pragma unroll
                for (int it = 0; it < 2; it++) {
                    int rl  = it * 4 + (lane >> 3);         // 0..7 row slot
                    int idx = 16 * mt + 8 * half + rl;      // warp-local row 0..31
                    float cu = __shfl_sync(0xffffffffu, m_cut, idx);
                    int   ai = __shfl_sync(0xffffffffu, m_ai,  idx);
                    int   aj = __shfl_sync(0xffffffffu, m_aj,  idx);
                    int p = p0 + rbase + idx;
                    if (p < P) {
                        int q = lane & 7;
                        float4 w = *(const float4*)(smc + wex + (uint32_t)rl * 144u + (uint32_t)q * 16u);
                        float4 hv = __ldg((const float4*)(g_h + (size_t)aj * F + cbase + q * 4));
                        float4 v;
                        v.x = w.x * cu * hv.x;
                        v.y = w.y * cu * hv.y;
                        v.z = w.z * cu * hv.z;
                        v.w = w.w * cu * hv.w;
                        red_add_v4(g_acc + (size_t)ai * F + cbase + q * 4, v);
                    }
                }
            }
    }
}

// ---------------------------------------------------------------- out = ssp(acc@Wo1+bo1)@Wo2 + bo2
// single 64KB weight buffer (Wo1 then Wo2), col-halved accumulators -> 2 CTAs/SM
#define SMO_WHI 0
#define SMO_WLO 32768
#define SMO_BO1 65536
#define SMO_BO2 66048
#define SMO_TOTAL 66560
__global__ __launch_bounds__(256, 2)
void k_output_mma(const float* __restrict__ bo1, const float* __restrict__ bo2,
                  float* __restrict__ out, int N) {
    extern __shared__ char smc[];
    const uint32_t sb = smem_u32(smc);
    const int tid = threadIdx.x, wid = tid >> 5, lane = tid & 31;
    const int l4 = lane >> 2, t2 = (lane & 3) * 2, mi = lane >> 3, l8 = lane & 7;
    {
        const uint4* s0 = (const uint4*)g_Wo1T[0]; uint4* d0 = (uint4*)(smc + SMO_WHI);
        for (int t = tid; t < 2048; t += 256) d0[t] = s0[t];
        const uint4* s1 = (const uint4*)g_Wo1T[1]; uint4* d1 = (uint4*)(smc + SMO_WLO);
        for (int t = tid; t < 2048; t += 256) d1[t] = s1[t];
        if (tid < 128) {
            ((float*)(smc + SMO_BO1))[tid] = bo1[tid];
            ((float*)(smc + SMO_BO2))[tid] = bo2[tid];
        }
    }
    __syncthreads();

    const int rA = blockIdx.x * 128 + 16 * wid + l4;
    const bool v0 = rA < N, v1 = rA + 8 < N;
    const uint32_t w2n = (uint32_t)((mi >> 1) * 8 + l8) * 256u;
    const float* b1s = (const float*)(smc + SMO_BO1);
    const float* b2s = (const float*)(smc + SMO_BO2);

    // ---- stage 1: T = ssp(g_acc @ Wo1 + bo1), col-halved -> a2 fragments ----
    uint32_t a2hi[32], a2lo[32];
    const float* a0 = g_acc + (size_t)rA * F;
    const float* a1 = a0 + (size_t)8 * F;
#pragma unroll 1
    for (int hc = 0; hc < 2; hc++) {
        float acc[8][4];
#pragma unroll
        for (int b = 0; b < 8; b++)
#pragma unroll
            for (int c = 0; c < 4; c++) acc[b][c] = 0.f;
#pragma unroll
        for (int j = 0; j < 8; j++) {
            float2 q0 = make_float2(0.f, 0.f), q1 = q0, q2 = q0, q3 = q0;
            if (v0) { q0 = *(const float2*)(a0 + 16 * j + t2); q2 = *(const float2*)(a0 + 16 * j + t2 + 8); }
            if (v1) { q1 = *(const float2*)(a1 + 16 * j + t2); q3 = *(const float2*)(a1 + 16 * j + t2 + 8); }
            uint32_t ah[4], al[4];
            split_pack(q0.x, q0.y, ah[0], al[0]);
            split_pack(q1.x, q1.y, ah[1], al[1]);
            split_pack(q2.x, q2.y, ah[2], al[2]);
            split_pack(q3.x, q3.y, ah[3], al[3]);
            const uint32_t kb = (uint32_t)(16 * j + (mi & 1) * 8);
            const uint32_t sw = (uint32_t)(((kb >> 3) ^ (uint32_t)l8) << 4);
#pragma unroll
            for (int ng = 0; ng < 4; ng++) {
                uint32_t off = (uint32_t)(16 * (4 * hc + ng)) * 256u + w2n + sw;
                uint32_t bh[4], bl[4];
                ldsm_x4(bh, sb + SMO_WHI + off);
                ldsm_x4(bl, sb + SMO_WLO + off);
                MMA6(acc[2 * ng], acc[2 * ng + 1], ah, al, bh, bl);
            }
        }
        // ssp + bias -> fragments for k-blocks j = 4*hc .. 4*hc+3
#pragma unroll
        for (int b = 0; b < 8; b++) {
            int c = 64 * hc + 8 * b + t2;
            float e0 = sspf(acc[b][0] + b1s[c]);
            float e1 = sspf(acc[b][1] + b1s[c + 1]);
            float e2 = sspf(acc[b][2] + b1s[c]);
            float e3 = sspf(acc[b][3] + b1s[c + 1]);
            split_pack(e0, e1, a2hi[16 * hc + 2 * b],     a2lo[16 * hc + 2 * b]);
            split_pack(e2, e3, a2hi[16 * hc + 2 * b + 1], a2lo[16 * hc + 2 * b + 1]);
        }
    }

    __syncthreads();   // all warps done reading Wo1 image
    {
        const uint4* s0 = (const uint4*)g_Wo2T[0]; uint4* d0 = (uint4*)(smc + SMO_WHI);
        for (int t = tid; t < 2048; t += 256) d0[t] = s0[t];
        const uint4* s1 = (const uint4*)g_Wo2T[1]; uint4* d1 = (uint4*)(smc + SMO_WLO);
        for (int t = tid; t < 2048; t += 256) d1[t] = s1[t];
    }
    __syncthreads();

    // ---- stage 2: out = T @ Wo2 + bo2, col-halved ----
#pragma unroll 1
    for (int hc = 0; hc < 2; hc++) {
        float acc[8][4];
#pragma unroll
        for (int b = 0; b < 8; b++)
#pragma unroll
            for (int c = 0; c < 4; c++) acc[b][c] = 0.f;
#pragma unroll
        for (int j = 0; j < 8; j++) {
            const uint32_t* ahf = a2hi + 4 * j;
            const uint32_t* alf = a2lo + 4 * j;
            const uint32_t kb = (uint32_t)(16 * j + (mi & 1) * 8);
            const uint32_t sw = (uint32_t)(((kb >> 3) ^ (uint32_t)l8) << 4);
#pragma unroll
            for (int ng = 0; ng < 4; ng++) {
                uint32_t off = (uint32_t)(16 * (4 * hc + ng)) * 256u + w2n + sw;
                uint32_t bh[4], bl[4];
                ldsm_x4(bh, sb + SMO_WHI + off);
                ldsm_x4(bl, sb + SMO_WLO + off);
                MMA6(acc[2 * ng], acc[2 * ng + 1], ahf, alf, bh, bl);
            }
        }
#pragma unroll
        for (int b = 0; b < 8; b++) {
            int c = 64 * hc + 8 * b + t2;
            if (v0) *(float2*)(out + (size_t)rA * F + c) =
                make_float2(acc[b][0] + b2s[c], acc[b][1] + b2s[c + 1]);
            if (v1) *(float2*)(out + (size_t)(rA + 8) * F + c) =
                make_float2(acc[b][2] + b2s[c], acc[b][3] + b2s[c + 1]);
        }
    }
}

// ----------------------------------------------------------------- launcher
extern "C" void kernel_launch(void* const* d_in, const int* in_sizes, int n_in,
                              void* d_out, int out_size) {
    const float* x    = (const float*)d_in[0];
    const int*   pl   = (const int*)  d_in[1];
    const float* f_ij = (const float*)d_in[2];
    const float* fcut = (const float*)d_in[3];
    const float* Win  = (const float*)d_in[4];
    const float* Wf1  = (const float*)d_in[5];
    const float* bf1  = (const float*)d_in[6];
    const float* Wf2  = (const float*)d_in[7];
    const float* bf2  = (const float*)d_in[8];
    const float* Wo1  = (const float*)d_in[9];
    const float* bo1  = (const float*)d_in[10];
    const float* Wo2  = (const float*)d_in[11];
    const float* bo2  = (const float*)d_in[12];
    float* out = (float*)d_out;

    const int N = in_sizes[0] / F;
    const int P = in_sizes[1] / 2;
    const int ntiles = (P + TP - 1) / TP;
    const int nrow_tiles = (N + 127) / 128;

    cudaFuncSetAttribute(k_input_mma,  cudaFuncAttributeMaxDynamicSharedMemorySize, SMI_TOTAL);
    cudaFuncSetAttribute(k_pairs_mma,  cudaFuncAttributeMaxDynamicSharedMemorySize, SM_PAIR_TOTAL);
    cudaFuncSetAttribute(k_output_mma, cudaFuncAttributeMaxDynamicSharedMemorySize, SMO_TOTAL);

    const int n4 = N * F / 4;
    k_prep<<<296, 256>>>(Wf2, Win, Wo1, Wo2, n4);
    k_input_mma<<<nrow_tiles, 256, SMI_TOTAL>>>(x, N);
    int grid = ntiles < 296 ? ntiles : 296;
    k_pairs_mma<<<grid, 256, SM_PAIR_TOTAL>>>(f_ij, fcut, pl, P, ntiles, Wf1, bf1, bf2);
    k_output_mma<<<nrow_tiles, 256, SMO_TOTAL>>>(bo1, bo2, out, N);
}

// round 17
// speedup vs baseline: 1.5750x; 1.0886x over previous
#include <cuda_runtime.h>
#include <cuda_bf16.h>
#include <cstdint>
#include <math.h>

#define F   128
#define R   32
#define TP  128      // pairs per tile in k_pairs (8 warps x 16 rows)
#define NT  256

// ---------------------------------------------------------------- scratch
__device__ float g_h  [100000 * 128];
__device__ float g_acc[100000 * 128];
__device__ unsigned char g_W1T [2][10240];  // Wf1^T [n=128][k=32] bf16 hi/lo, 80B rows (ldsm conflict-free)
__device__ unsigned char g_W2T [2][32768];  // Wf2^T [n][k] bf16 hi/lo, 256B rows, XOR-swizzled
__device__ unsigned char g_WinT[2][32768];  // W_in^T
__device__ unsigned char g_Wo1T[2][32768];  // Wo1^T
__device__ unsigned char g_Wo2T[2][32768];  // Wo2^T

// ---------------------------------------------------------------- helpers
__device__ __forceinline__ uint32_t smem_u32(const void* p) {
    uint32_t a;
    asm("{ .reg .u64 t; cvta.to.shared.u64 t, %1; cvt.u32.u64 %0, t; }" : "=r"(a) : "l"(p));
    return a;
}
__device__ __forceinline__ float sspf(float x) {
    float e = __expf(-fabsf(x));
    return fmaxf(x, 0.0f) + __logf(1.0f + e) - 0.6931471805599453f;
}
__device__ __forceinline__ void red_add_v4(float* p, float4 v) {
    asm volatile("red.global.add.v4.f32 [%0], {%1,%2,%3,%4};"
                 :: "l"(p), "f"(v.x), "f"(v.y), "f"(v.z), "f"(v.w) : "memory");
}
__device__ __forceinline__ void split_pack(float a, float b, uint32_t& hi, uint32_t& lo) {
    __nv_bfloat16 ah = __float2bfloat16(a), bh = __float2bfloat16(b);
    float ar = a - __bfloat162float(ah);
    float br = b - __bfloat162float(bh);
    __nv_bfloat16 al = __float2bfloat16(ar), bl = __float2bfloat16(br);
    hi = ((uint32_t)__bfloat16_as_ushort(bh) << 16) | (uint32_t)__bfloat16_as_ushort(ah);
    lo = ((uint32_t)__bfloat16_as_ushort(bl) << 16) | (uint32_t)__bfloat16_as_ushort(al);
}
__device__ __forceinline__ void mma16816(float* c, const uint32_t* a, const uint32_t* b) {
    asm volatile("mma.sync.aligned.m16n8k16.row.col.f32.bf16.bf16.f32 "
                 "{%0,%1,%2,%3}, {%4,%5,%6,%7}, {%8,%9}, {%0,%1,%2,%3};"
                 : "+f"(c[0]), "+f"(c[1]), "+f"(c[2]), "+f"(c[3])
                 : "r"(a[0]), "r"(a[1]), "r"(a[2]), "r"(a[3]), "r"(b[0]), "r"(b[1]));
}
__device__ __forceinline__ void ldsm_x4(uint32_t* r, uint32_t addr) {
    asm volatile("ldmatrix.sync.aligned.m8n8.x4.shared.b16 {%0,%1,%2,%3}, [%4];"
                 : "=r"(r[0]), "=r"(r[1]), "=r"(r[2]), "=r"(r[3]) : "r"(addr));
}
// interleaved 3-term split MMA: chains c0/c1 alternate (dep distance 2)
#define MMA6(c0, c1, ah, al, bh, bl) do {          \
    mma16816(c0, ah, bh);                          \
    mma16816(c1, ah, (bh) + 2);                    \
    mma16816(c0, al, bh);                          \
    mma16816(c1, al, (bh) + 2);                    \
    mma16816(c0, ah, bl);                          \
    mma16816(c1, ah, (bl) + 2); } while (0)

// ---------------------------------------------------------------- prep: weight images + zero g_acc
__global__ void k_prep(const float* __restrict__ Wf1, const float* __restrict__ Wf2,
                       const float* __restrict__ Win,
                       const float* __restrict__ Wo1, const float* __restrict__ Wo2,
                       int n4) {
    int idx = blockIdx.x * blockDim.x + threadIdx.x;
    if (idx < 16384) {
        int k = idx >> 7, n = idx & 127;
        uint32_t off = (uint32_t)n * 256u + ((uint32_t)((k >> 3) ^ (n & 7)) << 4) + (uint32_t)(k & 7) * 2u;
        {
            float w = Wf2[idx];
            __nv_bfloat16 h = __float2bfloat16(w);
            *(__nv_bfloat16*)(g_W2T[0] + off) = h;
            *(__nv_bfloat16*)(g_W2T[1] + off) = __float2bfloat16(w - __bfloat162float(h));
        }
        {
            float w = Win[idx];
            __nv_bfloat16 h = __float2bfloat16(w);
            *(__nv_bfloat16*)(g_WinT[0] + off) = h;
            *(__nv_bfloat16*)(g_WinT[1] + off) = __float2bfloat16(w - __bfloat162float(h));
        }
        {
            float w = Wo1[idx];
            __nv_bfloat16 h = __float2bfloat16(w);
            *(__nv_bfloat16*)(g_Wo1T[0] + off) = h;
            *(__nv_bfloat16*)(g_Wo1T[1] + off) = __float2bfloat16(w - __bfloat162float(h));
        }
        {
            float w = Wo2[idx];
            __nv_bfloat16 h = __float2bfloat16(w);
            *(__nv_bfloat16*)(g_Wo2T[0] + off) = h;
            *(__nv_bfloat16*)(g_Wo2T[1] + off) = __float2bfloat16(w - __bfloat162float(h));
        }
    }
    if (idx < 4096) {                  // Wf1 [k=32][n=128] -> [n][k], 80B rows
        int k = idx >> 7, n = idx & 127;
        float w = Wf1[idx];
        __nv_bfloat16 h = __float2bfloat16(w);
        uint32_t off = (uint32_t)n * 80u + (uint32_t)k * 2u;
        *(__nv_bfloat16*)(g_W1T[0] + off) = h;
        *(__nv_bfloat16*)(g_W1T[1] + off) = __float2bfloat16(w - __bfloat162float(h));
    }
    // zero segment-sum accumulator (grid-stride)
    const int stride = gridDim.x * blockDim.x;
    for (int i = idx; i < n4; i += stride)
        reinterpret_cast<float4*>(g_acc)[i] = make_float4(0.f, 0.f, 0.f, 0.f);
}

// ---------------------------------------------------------------- h = x @ W_in (mma bf16-split)
#define SMI_HI 0
#define SMI_LO 32768
#define SMI_TOTAL 65536
__global__ __launch_bounds__(256, 2)
void k_input_mma(const float* __restrict__ x, int N) {
    extern __shared__ char smc[];
    const uint32_t sb = smem_u32(smc);
    const int tid = threadIdx.x, wid = tid >> 5, lane = tid & 31;
    const int l4 = lane >> 2, t2 = (lane & 3) * 2, mi = lane >> 3, l8 = lane & 7;
    {
        const uint4* s0 = (const uint4*)g_WinT[0]; uint4* d0 = (uint4*)(smc + SMI_HI);
        for (int t = tid; t < 2048; t += 256) d0[t] = s0[t];
        const uint4* s1 = (const uint4*)g_WinT[1]; uint4* d1 = (uint4*)(smc + SMI_LO);
        for (int t = tid; t < 2048; t += 256) d1[t] = s1[t];
    }
    __syncthreads();

    const int rA = blockIdx.x * 128 + 16 * wid + l4;
    const bool v0 = rA < N, v1 = rA + 8 < N;
    const uint32_t w2n = (uint32_t)((mi >> 1) * 8 + l8) * 256u;

    float acc[16][4];
#pragma unroll
    for (int b = 0; b < 16; b++)
#pragma unroll
        for (int c = 0; c < 4; c++) acc[b][c] = 0.f;

    const float* x0 = x + (size_t)rA * F;
    const float* x1 = x0 + (size_t)8 * F;
#pragma unroll
    for (int j = 0; j < 8; j++) {
        float2 q0 = make_float2(0.f, 0.f), q1 = q0, q2 = q0, q3 = q0;
        if (v0) { q0 = *(const float2*)(x0 + 16 * j + t2); q2 = *(const float2*)(x0 + 16 * j + t2 + 8); }
        if (v1) { q1 = *(const float2*)(x1 + 16 * j + t2); q3 = *(const float2*)(x1 + 16 * j + t2 + 8); }
        uint32_t ah[4], al[4];
        split_pack(q0.x, q0.y, ah[0], al[0]);
        split_pack(q1.x, q1.y, ah[1], al[1]);
        split_pack(q2.x, q2.y, ah[2], al[2]);
        split_pack(q3.x, q3.y, ah[3], al[3]);
        const uint32_t kb = (uint32_t)(16 * j + (mi & 1) * 8);
        const uint32_t sw = (uint32_t)(((kb >> 3) ^ (uint32_t)l8) << 4);
#pragma unroll
        for (int ng = 0; ng < 8; ng++) {
            uint32_t off = (uint32_t)(16 * ng) * 256u + w2n + sw;
            uint32_t bh[4], bl[4];
            ldsm_x4(bh, sb + SMI_HI + off);
            ldsm_x4(bl, sb + SMI_LO + off);
            MMA6(acc[2 * ng], acc[2 * ng + 1], ah, al, bh, bl);
        }
    }
#pragma unroll
    for (int b = 0; b < 16; b++) {
        int c = 8 * b + t2;
        if (v0) *(float2*)(g_h + (size_t)rA * F + c)       = make_float2(acc[b][0], acc[b][1]);
        if (v1) *(float2*)(g_h + (size_t)(rA + 8) * F + c) = make_float2(acc[b][2], acc[b][3]);
    }
}

// ---------------------------------------------------------------- pair kernel: barrier-free, register C->A identity,
// col-halved stages (k_output economy). 8 warps x 16 rows, no inter-warp exchange.
// SMEM: W1hi 10240 | W1lo 10240 | W2hi 32K | W2lo 32K | WEX 8x2304 | bf1 512 | bf2 512
#define SM_W1HI 0
#define SM_W1LO 10240
#define SM_W2HI 20480
#define SM_W2LO 53248
#define SM_WEX  86016
#define SM_BF1  104448
#define SM_BF2  104960
#define SM_PAIR_TOTAL 105472

__global__ __launch_bounds__(256, 2)
void k_pairs_mma(const float* __restrict__ f_ij, const float* __restrict__ fcut,
                 const int* __restrict__ pairlist, int P, int ntiles,
                 const float* __restrict__ bf1, const float* __restrict__ bf2) {
    extern __shared__ char smc[];
    const uint32_t sb = smem_u32(smc);
    const int tid  = threadIdx.x;
    const int wid  = tid >> 5;
    const int lane = tid & 31;
    const int l4 = lane >> 2;
    const int t2 = (lane & 3) * 2;
    const int mi = lane >> 3;
    const int l8 = lane & 7;
    const uint32_t wex = SM_WEX + (uint32_t)wid * 2304u;   // 8 rows x 288B

    {
        const uint4* s0 = (const uint4*)g_W1T[0]; uint4* d0 = (uint4*)(smc + SM_W1HI);
        for (int t = tid; t < 640; t += 256) d0[t] = s0[t];
        const uint4* s1 = (const uint4*)g_W1T[1]; uint4* d1 = (uint4*)(smc + SM_W1LO);
        for (int t = tid; t < 640; t += 256) d1[t] = s1[t];
        const uint4* s2 = (const uint4*)g_W2T[0]; uint4* d2 = (uint4*)(smc + SM_W2HI);
        for (int t = tid; t < 2048; t += 256) d2[t] = s2[t];
        const uint4* s3 = (const uint4*)g_W2T[1]; uint4* d3 = (uint4*)(smc + SM_W2LO);
        for (int t = tid; t < 2048; t += 256) d3[t] = s3[t];
        if (tid < 128) {
            ((float*)(smc + SM_BF1))[tid] = bf1[tid];
            ((float*)(smc + SM_BF2))[tid] = bf2[tid];
        }
    }
    const float* b1s = (const float*)(smc + SM_BF1);
    const float* b2s = (const float*)(smc + SM_BF2);
    const uint32_t w1n = (uint32_t)((mi >> 1) * 8 + l8) * 80u + (uint32_t)(mi & 1) * 16u;
    const uint32_t w2n = (uint32_t)((mi >> 1) * 8 + l8) * 256u;
    __syncthreads();   // the ONLY block-wide barrier

    for (int tile = blockIdx.x; tile < ntiles; tile += gridDim.x) {
        const int p0 = tile * TP;
        const int rA = p0 + 16 * wid + l4;
        const bool v0 = rA < P, v1 = rA + 8 < P;

        // metadata: lanes 0..15 hold the warp's 16 rows
        float m_cut = 0.f; int m_ai = 0, m_aj = 0;
        if (lane < 16) {
            int pm = p0 + 16 * wid + lane;
            if (pm < P) {
                m_cut = __ldg(fcut + pm);
                m_ai  = __ldg(pairlist + pm);
                m_aj  = __ldg(pairlist + (size_t)P + pm);
            }
        }

        // A1 fragments from gmem (K=32)
        uint32_t a1h[2][4], a1l[2][4];
#pragma unroll
        for (int ks = 0; ks < 2; ks++) {
            float2 q0 = make_float2(0.f, 0.f), q1 = q0, q2 = q0, q3 = q0;
            if (v0) {
                const float* fp = f_ij + (size_t)rA * R + 16 * ks + t2;
                q0 = *(const float2*)fp;
                q2 = *(const float2*)(fp + 8);
            }
            if (v1) {
                const float* fp = f_ij + (size_t)(rA + 8) * R + 16 * ks + t2;
                q1 = *(const float2*)fp;
                q3 = *(const float2*)(fp + 8);
            }
            split_pack(q0.x, q0.y, a1h[ks][0], a1l[ks][0]);
            split_pack(q1.x, q1.y, a1h[ks][1], a1l[ks][1]);
            split_pack(q2.x, q2.y, a1h[ks][2], a1l[ks][2]);
            split_pack(q3.x, q3.y, a1h[ks][3], a1l[ks][3]);
        }

        // ---- stage 1: S = ssp(f_ij @ W1 + bf1), col-halved -> a2 fragments in regs ----
        uint32_t a2hi[32], a2lo[32];
#pragma unroll 1
        for (int hc = 0; hc < 2; hc++) {
            float acc8[8][4];
#pragma unroll
            for (int b = 0; b < 8; b++)
#pragma unroll
                for (int c = 0; c < 4; c++) acc8[b][c] = 0.f;
#pragma unroll
            for (int ks = 0; ks < 2; ks++) {
                const uint32_t kofs = (uint32_t)(32 * ks);   // 16 cols * 2B
#pragma unroll
                for (int ngl = 0; ngl < 4; ngl++) {
                    int ng = 4 * hc + ngl;
                    uint32_t off = (uint32_t)(16 * ng) * 80u + w1n + kofs;
                    uint32_t bh[4], bl[4];
                    ldsm_x4(bh, sb + SM_W1HI + off);
                    ldsm_x4(bl, sb + SM_W1LO + off);
                    MMA6(acc8[2 * ngl], acc8[2 * ngl + 1], a1h[ks], a1l[ks], bh, bl);
                }
            }
#pragma unroll
            for (int b = 0; b < 8; b++) {
                int c = 64 * hc + 8 * b + t2;
                float e0 = sspf(acc8[b][0] + b1s[c]);
                float e1 = sspf(acc8[b][1] + b1s[c + 1]);
                float e2 = sspf(acc8[b][2] + b1s[c]);
                float e3 = sspf(acc8[b][3] + b1s[c + 1]);
                split_pack(e0, e1, a2hi[16 * hc + 2 * b],     a2lo[16 * hc + 2 * b]);
                split_pack(e2, e3, a2hi[16 * hc + 2 * b + 1], a2lo[16 * hc + 2 * b + 1]);
            }
        }

        // ---- stage 2: W_ij = S @ W2 (K=128), col-halved, epilogue fused per half ----
#pragma unroll 1
        for (int hc2 = 0; hc2 < 2; hc2++) {
            float acc8[8][4];
#pragma unroll
            for (int b = 0; b < 8; b++)
#pragma unroll
                for (int c = 0; c < 4; c++) acc8[b][c] = 0.f;
#pragma unroll 2
            for (int j = 0; j < 8; j++) {
                const uint32_t kb = (uint32_t)(16 * j + (mi & 1) * 8);
                const uint32_t sw = (uint32_t)(((kb >> 3) ^ (uint32_t)l8) << 4);
                const uint32_t* ahf = a2hi + 4 * j;
                const uint32_t* alf = a2lo + 4 * j;
#pragma unroll
                for (int ngl = 0; ngl < 4; ngl++) {
                    int ng = 4 * hc2 + ngl;
                    uint32_t off = (uint32_t)(16 * ng) * 256u + w2n + sw;
                    uint32_t bh[4], bl[4];
                    ldsm_x4(bh, sb + SM_W2HI + off);
                    ldsm_x4(bl, sb + SM_W2LO + off);
                    MMA6(acc8[2 * ngl], acc8[2 * ngl + 1], ahf, alf, bh, bl);
                }
            }

            // epilogue for cols 64*hc2 .. +63, two 8-row passes, warp-local transpose
#pragma unroll
            for (int rp = 0; rp < 2; rp++) {
                __syncwarp();
#pragma unroll
                for (int b = 0; b < 8; b++) {
                    int c = 64 * hc2 + 8 * b + t2;
                    *(float2*)(smc + wex + (uint32_t)l4 * 288u + (uint32_t)(8 * b + t2) * 4u) =
                        make_float2(acc8[b][2 * rp]     + b2s[c],
                                    acc8[b][2 * rp + 1] + b2s[c + 1]);
                }
                __syncwarp();
#pragma unroll
                for (int it = 0; it < 4; it++) {
                    int rl  = it * 2 + (lane >> 4);         // 0..7 row slot
                    int idx = 8 * rp + rl;                  // warp-local row 0..15
                    float cu = __shfl_sync(0xffffffffu, m_cut, idx);
                    int   ai = __shfl_sync(0xffffffffu, m_ai,  idx);
                    int   aj = __shfl_sync(0xffffffffu, m_aj,  idx);
                    int p = p0 + 16 * wid + idx;
                    if (p < P) {
                        int q = lane & 15;
                        float4 w = *(const float4*)(smc + wex + (uint32_t)rl * 288u + (uint32_t)q * 16u);
                        float4 hv = __ldg((const float4*)(g_h + (size_t)aj * F + 64 * hc2 + q * 4));
                        float4 v;
                        v.x = w.x * cu * hv.x;
                        v.y = w.y * cu * hv.y;
                        v.z = w.z * cu * hv.z;
                        v.w = w.w * cu * hv.w;
                        red_add_v4(g_acc + (size_t)ai * F + 64 * hc2 + q * 4, v);
                    }
                }
            }
        }
    }
}

// ---------------------------------------------------------------- out = ssp(acc@Wo1+bo1)@Wo2 + bo2
// single 64KB weight buffer (Wo1 then Wo2), col-halved accumulators -> 2 CTAs/SM
#define SMO_WHI 0
#define SMO_WLO 32768
#define SMO_BO1 65536
#define SMO_BO2 66048
#define SMO_TOTAL 66560
__global__ __launch_bounds__(256, 2)
void k_output_mma(const float* __restrict__ bo1, const float* __restrict__ bo2,
                  float* __restrict__ out, int N) {
    extern __shared__ char smc[];
    const uint32_t sb = smem_u32(smc);
    const int tid = threadIdx.x, wid = tid >> 5, lane = tid & 31;
    const int l4 = lane >> 2, t2 = (lane & 3) * 2, mi = lane >> 3, l8 = lane & 7;
    {
        const uint4* s0 = (const uint4*)g_Wo1T[0]; uint4* d0 = (uint4*)(smc + SMO_WHI);
        for (int t = tid; t < 2048; t += 256) d0[t] = s0[t];
        const uint4* s1 = (const uint4*)g_Wo1T[1]; uint4* d1 = (uint4*)(smc + SMO_WLO);
        for (int t = tid; t < 2048; t += 256) d1[t] = s1[t];
        if (tid < 128) {
            ((float*)(smc + SMO_BO1))[tid] = bo1[tid];
            ((float*)(smc + SMO_BO2))[tid] = bo2[tid];
        }
    }
    __syncthreads();

    const int rA = blockIdx.x * 128 + 16 * wid + l4;
    const bool v0 = rA < N, v1 = rA + 8 < N;
    const uint32_t w2n = (uint32_t)((mi >> 1) * 8 + l8) * 256u;
    const float* b1s = (const float*)(smc + SMO_BO1);
    const float* b2s = (const float*)(smc + SMO_BO2);

    uint32_t a2hi[32], a2lo[32];
    const float* a0 = g_acc + (size_t)rA * F;
    const float* a1 = a0 + (size_t)8 * F;
#pragma unroll 1
    for (int hc = 0; hc < 2; hc++) {
        float acc[8][4];
#pragma unroll
        for (int b = 0; b < 8; b++)
#pragma unroll
            for (int c = 0; c < 4; c++) acc[b][c] = 0.f;
#pragma unroll
        for (int j = 0; j < 8; j++) {
            float2 q0 = make_float2(0.f, 0.f), q1 = q0, q2 = q0, q3 = q0;
            if (v0) { q0 = *(const float2*)(a0 + 16 * j + t2); q2 = *(const float2*)(a0 + 16 * j + t2 + 8); }
            if (v1) { q1 = *(const float2*)(a1 + 16 * j + t2); q3 = *(const float2*)(a1 + 16 * j + t2 + 8); }
            uint32_t ah[4], al[4];
            split_pack(q0.x, q0.y, ah[0], al[0]);
            split_pack(q1.x, q1.y, ah[1], al[1]);
            split_pack(q2.x, q2.y, ah[2], al[2]);
            split_pack(q3.x, q3.y, ah[3], al[3]);
            const uint32_t kb = (uint32_t)(16 * j + (mi & 1) * 8);
            const uint32_t sw = (uint32_t)(((kb >> 3) ^ (uint32_t)l8) << 4);
#pragma unroll
            for (int ng = 0; ng < 4; ng++) {
                uint32_t off = (uint32_t)(16 * (4 * hc + ng)) * 256u + w2n + sw;
                uint32_t bh[4], bl[4];
                ldsm_x4(bh, sb + SMO_WHI + off);
                ldsm_x4(bl, sb + SMO_WLO + off);
                MMA6(acc[2 * ng], acc[2 * ng + 1], ah, al, bh, bl);
            }
        }
#pragma unroll
        for (int b = 0; b < 8; b++) {
            int c = 64 * hc + 8 * b + t2;
            float e0 = sspf(acc[b][0] + b1s[c]);
            float e1 = sspf(acc[b][1] + b1s[c + 1]);
            float e2 = sspf(acc[b][2] + b1s[c]);
            float e3 = sspf(acc[b][3] + b1s[c + 1]);
            split_pack(e0, e1, a2hi[16 * hc + 2 * b],     a2lo[16 * hc + 2 * b]);
            split_pack(e2, e3, a2hi[16 * hc + 2 * b + 1], a2lo[16 * hc + 2 * b + 1]);
        }
    }

    __syncthreads();   // all warps done reading Wo1 image
    {
        const uint4* s0 = (const uint4*)g_Wo2T[0]; uint4* d0 = (uint4*)(smc + SMO_WHI);
        for (int t = tid; t < 2048; t += 256) d0[t] = s0[t];
        const uint4* s1 = (const uint4*)g_Wo2T[1]; uint4* d1 = (uint4*)(smc + SMO_WLO);
        for (int t = tid; t < 2048; t += 256) d1[t] = s1[t];
    }
    __syncthreads();

#pragma unroll 1
    for (int hc = 0; hc < 2; hc++) {
        float acc[8][4];
#pragma unroll
        for (int b = 0; b < 8; b++)
#pragma unroll
            for (int c = 0; c < 4; c++) acc[b][c] = 0.f;
#pragma unroll
        for (int j = 0; j < 8; j++) {
            const uint32_t* ahf = a2hi + 4 * j;
            const uint32_t* alf = a2lo + 4 * j;
            const uint32_t kb = (uint32_t)(16 * j + (mi & 1) * 8);
            const uint32_t sw = (uint32_t)(((kb >> 3) ^ (uint32_t)l8) << 4);
#pragma unroll
            for (int ng = 0; ng < 4; ng++) {
                uint32_t off = (uint32_t)(16 * (4 * hc + ng)) * 256u + w2n + sw;
                uint32_t bh[4], bl[4];
                ldsm_x4(bh, sb + SMO_WHI + off);
                ldsm_x4(bl, sb + SMO_WLO + off);
                MMA6(acc[2 * ng], acc[2 * ng + 1], ahf, alf, bh, bl);
            }
        }
#pragma unroll
        for (int b = 0; b < 8; b++) {
            int c = 64 * hc + 8 * b + t2;
            if (v0) *(float2*)(out + (size_t)rA * F + c) =
                make_float2(acc[b][0] + b2s[c], acc[b][1] + b2s[c + 1]);
            if (v1) *(float2*)(out + (size_t)(rA + 8) * F + c) =
                make_float2(acc[b][2] + b2s[c], acc[b][3] + b2s[c + 1]);
        }
    }
}

// ----------------------------------------------------------------- launcher
extern "C" void kernel_launch(void* const* d_in, const int* in_sizes, int n_in,
                              void* d_out, int out_size) {
    const float* x    = (const float*)d_in[0];
    const int*   pl   = (const int*)  d_in[1];
    const float* f_ij = (const float*)d_in[2];
    const float* fcut = (const float*)d_in[3];
    const float* Win  = (const float*)d_in[4];
    const float* Wf1  = (const float*)d_in[5];
    const float* bf1  = (const float*)d_in[6];
    const float* Wf2  = (const float*)d_in[7];
    const float* bf2  = (const float*)d_in[8];
    const float* Wo1  = (const float*)d_in[9];
    const float* bo1  = (const float*)d_in[10];
    const float* Wo2  = (const float*)d_in[11];
    const float* bo2  = (const float*)d_in[12];
    float* out = (float*)d_out;

    const int N = in_sizes[0] / F;
    const int P = in_sizes[1] / 2;
    const int ntiles = (P + TP - 1) / TP;
    const int nrow_tiles = (N + 127) / 128;

    cudaFuncSetAttribute(k_input_mma,  cudaFuncAttributeMaxDynamicSharedMemorySize, SMI_TOTAL);
    cudaFuncSetAttribute(k_pairs_mma,  cudaFuncAttributeMaxDynamicSharedMemorySize, SM_PAIR_TOTAL);
    cudaFuncSetAttribute(k_output_mma, cudaFuncAttributeMaxDynamicSharedMemorySize, SMO_TOTAL);

    const int n4 = N * F / 4;
    k_prep<<<296, 256>>>(Wf1, Wf2, Win, Wo1, Wo2, n4);
    k_input_mma<<<nrow_tiles, 256, SMI_TOTAL>>>(x, N);
    int grid = ntiles < 296 ? ntiles : 296;
    k_pairs_mma<<<grid, 256, SM_PAIR_TOTAL>>>(f_ij, fcut, pl, P, ntiles, bf1, bf2);
    k_output_mma<<<nrow_tiles, 256, SMO_TOTAL>>>(bo1, bo2, out, N);
}